// round 13
// baseline (speedup 1.0000x reference)
#include <cuda_runtime.h>
#include <cstdint>

// Problem constants: b=2, h=16, L=4096, d=128, chunk=32
#define NTILES   4096
#define OUT_ELEMS 16777216
#define S_ELEMS   524288
#define PW 132                   // padded stride for 128-wide rows
#define PS 36                    // padded stride for 32-wide rows

typedef unsigned long long u64;

// Scratch (static device globals). g_w holds NEGATED w.
__device__ float g_qn[16777216];
__device__ float g_kn[16777216];
__device__ float g_w [16777216];
__device__ float g_u [16777216];
__device__ float g_attn[4194304];

#define FMA2(d, a, b, c) asm("fma.rn.f32x2 %0, %1, %2, %3;" : "=l"(d) : "l"(a), "l"(b), "l"(c))
#define ADD2(d, a, b)    asm("add.rn.f32x2 %0, %1, %2;"     : "=l"(d) : "l"(a), "l"(b))
#define PK2(d, lo, hi)   asm("mov.b64 %0, {%1, %2};"        : "=l"(d) : "f"(lo), "f"(hi))
#define UPK2(lo, hi, s)  asm("mov.b64 {%0, %1}, %2;"        : "=f"(lo), "=f"(hi) : "l"(s))

__device__ __forceinline__ void cpa16(float* dst_smem, const float* src_gmem) {
    uint32_t d = (uint32_t)__cvta_generic_to_shared(dst_smem);
    asm volatile("cp.async.cg.shared.global [%0], [%1], 16;\n" :: "r"(d), "l"(src_gmem));
}
#define CP_COMMIT() asm volatile("cp.async.commit_group;\n" ::: "memory")
#define CP_WAIT0()  asm volatile("cp.async.wait_group 0;\n" ::: "memory")

// 32x32 matmul on shared (stride-32): out = (adds? adds:0) + a @ b   (f32x2)
__device__ __forceinline__ void mm32(float* __restrict__ out,
                                     const float* __restrict__ a,
                                     const float* __restrict__ b,
                                     const float* __restrict__ adds,
                                     int tid) {
    int i  = tid >> 3;
    int j4 = (tid & 7) << 2;
    float ar[32];
#pragma unroll
    for (int c = 0; c < 8; c++) {
        float4 t = *(const float4*)(a + i * 32 + c * 4);
        ar[c*4+0] = t.x; ar[c*4+1] = t.y; ar[c*4+2] = t.z; ar[c*4+3] = t.w;
    }
    u64 acc01 = 0, acc23 = 0;
    if (adds) {
        ulonglong2 ad = *(const ulonglong2*)(adds + i * 32 + j4);
        acc01 = ad.x; acc23 = ad.y;
    }
#pragma unroll
    for (int kk = 0; kk < 32; kk++) {
        ulonglong2 b2 = *(const ulonglong2*)(b + kk * 32 + j4);
        u64 a2; PK2(a2, ar[kk], ar[kk]);
        FMA2(acc01, a2, b2.x, acc01);
        FMA2(acc23, a2, b2.y, acc23);
    }
    ulonglong2 o; o.x = acc01; o.y = acc23;
    *(ulonglong2*)(out + i * 32 + j4) = o;
}

// ---------------------------------------------------------------------------
// Kernel 1: per chunk-tile (4096 CTAs). (round-6 version)
// ---------------------------------------------------------------------------
extern __shared__ float sm1[];

__global__ void __launch_bounds__(256, 3)
k1_kernel(const float* __restrict__ q, const float* __restrict__ k,
          const float* __restrict__ v, const float* __restrict__ beta) {
    float* qn   = sm1;               // 32*PW
    float* kn   = qn + 32 * PW;      // 32*PW
    float* vbkt = kn + 32 * PW;      // 32*PW  (kt first, vb later)
    float* Am = vbkt + 32 * PW;      // 1024
    float* Bm = Am + 1024;
    float* Xm = Bm + 1024;
    float* Ym = Xm + 1024;
    float* beta_s  = Ym + 1024;      // 32
    float* nbeta_s = beta_s + 32;    // 32

    const int tid  = threadIdx.x;
    const int tile = blockIdx.x;
    const size_t base = (size_t)tile * 4096;
    const int brow = tile * 32;

    {
        int wp = tid >> 5, lane = tid & 31;
#pragma unroll
        for (int rr = 0; rr < 4; rr++) {
            int r = wp * 4 + rr;
            float4 a = *(const float4*)(q + base + r * 128 + lane * 4);
            float s = a.x*a.x + a.y*a.y + a.z*a.z + a.w*a.w;
#pragma unroll
            for (int off = 16; off; off >>= 1) s += __shfl_xor_sync(0xffffffffu, s, off);
            float sc = rsqrtf(s + 1e-6f);
            float4 o = make_float4(a.x*sc, a.y*sc, a.z*sc, a.w*sc);
            *(float4*)(qn + r * PW + lane * 4) = o;
            *(float4*)(g_qn + base + r * 128 + lane * 4) = o;

            float4 b = *(const float4*)(k + base + r * 128 + lane * 4);
            float sk = b.x*b.x + b.y*b.y + b.z*b.z + b.w*b.w;
#pragma unroll
            for (int off = 16; off; off >>= 1) sk += __shfl_xor_sync(0xffffffffu, sk, off);
            float sck = rsqrtf(sk + 1e-6f);
            float4 ok = make_float4(b.x*sck, b.y*sck, b.z*sck, b.w*sck);
            *(float4*)(kn + r * PW + lane * 4) = ok;
            *(float4*)(g_kn + base + r * 128 + lane * 4) = ok;
        }
        if (tid < 32) {
            float b = beta[brow + tid];
            beta_s[tid] = b;
            nbeta_s[tid] = -b;
        }
    }
    __syncthreads();

    // kt (128 x 32) into vbkt
    {
#pragma unroll
        for (int t = 0; t < 4; t++) {
            int idx = tid + t * 256;
            int r = idx & 31, g = idx >> 5;
            float4 f = *(const float4*)(kn + r * PW + g * 4);
            vbkt[(4*g+0) * 32 + r] = f.x;
            vbkt[(4*g+1) * 32 + r] = f.y;
            vbkt[(4*g+2) * 32 + r] = f.z;
            vbkt[(4*g+3) * 32 + r] = f.w;
        }
    }
    __syncthreads();

    // T0/attn
    {
        const float* kt = vbkt;
        const int h  = tid >> 7;
        const int t  = tid & 127;
        const int r0 = (t >> 3) * 2, r1 = r0 + 1;
        const int j4 = (t & 7) << 2;
        u64 aK0a=0,aK0b=0,aK1a=0,aK1b=0, aQ0a=0,aQ0b=0,aQ1a=0,aQ1b=0;
        const int c0 = h * 64;
#pragma unroll 4
        for (int c = c0; c < c0 + 64; c++) {
            ulonglong2 kt2 = *(const ulonglong2*)(kt + c * 32 + j4);
            float k0v = kn[r0*PW + c], k1v = kn[r1*PW + c];
            float q0v = qn[r0*PW + c], q1v = qn[r1*PW + c];
            u64 k02,k12,q02,q12;
            PK2(k02,k0v,k0v); PK2(k12,k1v,k1v); PK2(q02,q0v,q0v); PK2(q12,q1v,q1v);
            FMA2(aK0a,k02,kt2.x,aK0a); FMA2(aK0b,k02,kt2.y,aK0b);
            FMA2(aK1a,k12,kt2.x,aK1a); FMA2(aK1b,k12,kt2.y,aK1b);
            FMA2(aQ0a,q02,kt2.x,aQ0a); FMA2(aQ0b,q02,kt2.y,aQ0b);
            FMA2(aQ1a,q12,kt2.x,aQ1a); FMA2(aQ1b,q12,kt2.y,aQ1b);
        }
        if (h == 1) {
            *(u64*)(Bm + r0*32 + j4)   = aK0a; *(u64*)(Bm + r0*32 + j4+2) = aK0b;
            *(u64*)(Bm + r1*32 + j4)   = aK1a; *(u64*)(Bm + r1*32 + j4+2) = aK1b;
            *(u64*)(Ym + r0*32 + j4)   = aQ0a; *(u64*)(Ym + r0*32 + j4+2) = aQ0b;
            *(u64*)(Ym + r1*32 + j4)   = aQ1a; *(u64*)(Ym + r1*32 + j4+2) = aQ1b;
        }
        __syncthreads();
        if (h == 0) {
            ADD2(aK0a, aK0a, *(const u64*)(Bm + r0*32 + j4));
            ADD2(aK0b, aK0b, *(const u64*)(Bm + r0*32 + j4+2));
            ADD2(aK1a, aK1a, *(const u64*)(Bm + r1*32 + j4));
            ADD2(aK1b, aK1b, *(const u64*)(Bm + r1*32 + j4+2));
            ADD2(aQ0a, aQ0a, *(const u64*)(Ym + r0*32 + j4));
            ADD2(aQ0b, aQ0b, *(const u64*)(Ym + r0*32 + j4+2));
            ADD2(aQ1a, aQ1a, *(const u64*)(Ym + r1*32 + j4));
            ADD2(aQ1b, aQ1b, *(const u64*)(Ym + r1*32 + j4+2));
            float K0[4], K1[4], Q0[4], Q1[4];
            UPK2(K0[0],K0[1],aK0a); UPK2(K0[2],K0[3],aK0b);
            UPK2(K1[0],K1[1],aK1a); UPK2(K1[2],K1[3],aK1b);
            UPK2(Q0[0],Q0[1],aQ0a); UPK2(Q0[2],Q0[3],aQ0b);
            UPK2(Q1[0],Q1[1],aQ1a); UPK2(Q1[2],Q1[3],aQ1b);
#pragma unroll
            for (int rr = 0; rr < 2; rr++) {
                int row = r0 + rr;
                const float* K = rr ? K1 : K0;
                const float* Q = rr ? Q1 : Q0;
                float bb = beta_s[row];
                float att[4];
#pragma unroll
                for (int m = 0; m < 4; m++) {
                    int j = j4 + m;
                    float t0 = (row > j) ? (-bb * K[m]) : 0.f;
                    Am[row*32 + j] = t0;
                    Xm[row*32 + j] = t0 + ((row == j) ? 1.f : 0.f);
                    att[m] = (row >= j) ? Q[m] : 0.f;
                }
                *(float4*)(g_attn + (size_t)tile * 1024 + row * 32 + j4) =
                    make_float4(att[0], att[1], att[2], att[3]);
            }
        }
        __syncthreads();
    }

    // (I - T0)^{-1} via nilpotent squaring
    float *Ap = Am, *Bp = Bm, *Xp = Xm, *Yp = Ym;
#pragma unroll 1
    for (int s = 0; s < 4; s++) {
        mm32(Bp, Ap, Ap, nullptr, tid);
        __syncthreads();
        mm32(Yp, Xp, Bp, Xp, tid);
        __syncthreads();
        float* t;
        t = Ap; Ap = Bp; Bp = t;
        t = Xp; Xp = Yp; Yp = t;
    }

    // vb = v * beta
    for (int x = tid; x < 1024; x += 256) {
        int r = x >> 5, c4 = (x & 31) << 2;
        float4 vv = *(const float4*)(v + base + r * 128 + c4);
        float bb = beta_s[r];
        *(float4*)(vbkt + r * PW + c4) = make_float4(vv.x*bb, vv.y*bb, vv.z*bb, vv.w*bb);
    }
    __syncthreads();

    // g_w = -(Xp @ (kn * beta)), g_u = Xp @ vb
    {
        int i  = tid >> 3;
        int jg = tid & 7;
        float xr[32];
#pragma unroll
        for (int c = 0; c < 8; c++) {
            float4 t = *(const float4*)(Xp + i * 32 + c * 4);
            xr[c*4+0] = t.x; xr[c*4+1] = t.y; xr[c*4+2] = t.z; xr[c*4+3] = t.w;
        }

#pragma unroll 1
        for (int cblk = 0; cblk < 4; cblk++) {
            int c = cblk * 32 + jg * 4;
            u64 w01 = 0, w23 = 0, u01 = 0, u23 = 0;
#pragma unroll
            for (int kk = 0; kk < 32; kk++) {
                ulonglong2 k2v = *(const ulonglong2*)(kn   + kk * PW + c);
                ulonglong2 v2v = *(const ulonglong2*)(vbkt + kk * PW + c);
                float xbv = xr[kk] * nbeta_s[kk];
                u64 xb2, xr2;
                PK2(xb2, xbv, xbv); PK2(xr2, xr[kk], xr[kk]);
                FMA2(w01, xb2, k2v.x, w01); FMA2(w23, xb2, k2v.y, w23);
                FMA2(u01, xr2, v2v.x, u01); FMA2(u23, xr2, v2v.y, u23);
            }
            ulonglong2 ow; ow.x = w01; ow.y = w23;
            ulonglong2 ou; ou.x = u01; ou.y = u23;
            *(ulonglong2*)(g_w + base + i * 128 + c) = ow;
            *(ulonglong2*)(g_u + base + i * 128 + c) = ou;
        }
    }
}

// ---------------------------------------------------------------------------
// Kernel 2: sequential scan, 1024 threads, K-split QUARTERS, f32x2, cp.async.
// ---------------------------------------------------------------------------
#define BUF_FLOATS (3 * 32 * PW + 2 * 32 * PS)   // 12672 + 2304 = 14976

extern __shared__ float sm2[];

__device__ __forceinline__ void k2_prefetch(int n, float* buf, int bh, int sl, int tid) {
    const size_t tb = ((size_t)bh * 128 + n) * 4096;
    float* w = buf;
    float* q = buf + 32 * PW;
    float* k = buf + 64 * PW;
    float* u = buf + 96 * PW;
    float* a = buf + 96 * PW + 32 * PS;
    {
        int r = tid >> 5, c4 = (tid & 31) << 2;   // tid 0..1023 covers all 1024 slots
        cpa16(w + r * PW + c4, g_w  + tb + r * 128 + c4);
        cpa16(q + r * PW + c4, g_qn + tb + r * 128 + c4);
        cpa16(k + r * PW + c4, g_kn + tb + r * 128 + c4);
    }
    if (tid < 256) {
        int r = tid >> 3, c4 = (tid & 7) << 2;
        cpa16(u + r * PS + c4, g_u + tb + r * 128 + sl * 32 + c4);
    } else if (tid < 512) {
        int t2 = tid - 256;
        int r = t2 >> 3, c4 = (t2 & 7) << 2;
        cpa16(a + r * PS + c4, g_attn + ((size_t)bh * 128 + n) * 1024 + r * 32 + c4);
    }
}

__global__ void __launch_bounds__(1024, 1)
k2_kernel(float* __restrict__ out, int out_size) {
    float* S    = sm2;                        // 128*PS = 4608
    float* uish = S + 128 * PS;               // 32*PS
    float* pA   = uish + 32 * PS;             // 3 * 32*PS
    float* pO   = pA + 3 * 32 * PS;           // 3 * 32*PS
    float* bufs = pO + 3 * 32 * PS;           // 2*BUF_FLOATS

    const int tid = threadIdx.x;
    const int sl  = blockIdx.x;
    const int bh  = blockIdx.z * 16 + blockIdx.y;
    const int h   = tid >> 8;                 // K-quarter 0..3
    const int t8  = tid & 255;
    const int i   = t8 >> 3;                  // row 0..31
    const int j4  = (t8 & 7) << 2;            // col group
    const int kb  = h * 32;                   // S-row base for this quarter
    const int ur0 = (tid >> 4) << 1;          // update rows: 0,2,...,126
    const int uj2 = (tid & 15) << 1;          // update col pair

    for (int x = tid; x < 128 * PS; x += 1024) S[x] = 0.f;

    k2_prefetch(0, bufs, bh, sl, tid);
    CP_COMMIT();

#pragma unroll 1
    for (int n = 0; n < 128; n++) {
        float* buf = bufs + (n & 1) * BUF_FLOATS;
        CP_WAIT0();
        __syncthreads();                                   // A
        if (n + 1 < 128) { k2_prefetch(n + 1, bufs + ((n + 1) & 1) * BUF_FLOATS, bh, sl, tid); CP_COMMIT(); }

        const float* w = buf;
        const float* q = buf + 32 * PW;
        const float* k = buf + 64 * PW;
        const float* u = buf + 96 * PW;
        const float* a = buf + 96 * PW + 32 * PS;

        // main: aui = [h0: u0] + (-w)@S_quarter ; ao = q@S_quarter   (f32x2)
        u64 aui01 = 0, aui23 = 0, ao01 = 0, ao23 = 0;
        if (h == 0) {
            ulonglong2 t = *(const ulonglong2*)(u + i * PS + j4);
            aui01 = t.x; aui23 = t.y;
        }
#pragma unroll 2
        for (int kk4 = 0; kk4 < 8; kk4++) {
            float4 w4 = *(const float4*)(w + i * PW + kb + kk4 * 4);
            float4 q4 = *(const float4*)(q + i * PW + kb + kk4 * 4);
#define MSTEP(m, wc, qc)                                                        \
            {                                                                   \
                ulonglong2 s2 = *(const ulonglong2*)(S + (kb + kk4*4 + m) * PS + j4); \
                u64 w2, q2; PK2(w2, wc, wc); PK2(q2, qc, qc);                   \
                FMA2(aui01, w2, s2.x, aui01); FMA2(aui23, w2, s2.y, aui23);     \
                FMA2(ao01,  q2, s2.x, ao01);  FMA2(ao23,  q2, s2.y, ao23);      \
            }
            MSTEP(0, w4.x, q4.x) MSTEP(1, w4.y, q4.y)
            MSTEP(2, w4.z, q4.z) MSTEP(3, w4.w, q4.w)
#undef MSTEP
        }
        if (h != 0) {
            float* mA = pA + (h - 1) * 32 * PS;
            float* mO = pO + (h - 1) * 32 * PS;
            *(u64*)(mA + i * PS + j4)     = aui01;
            *(u64*)(mA + i * PS + j4 + 2) = aui23;
            *(u64*)(mO + i * PS + j4)     = ao01;
            *(u64*)(mO + i * PS + j4 + 2) = ao23;
        }
        __syncthreads();                                   // B
        if (h == 0) {
#pragma unroll
            for (int g = 0; g < 3; g++) {
                ADD2(aui01, aui01, *(const u64*)(pA + g * 32 * PS + i * PS + j4));
                ADD2(aui23, aui23, *(const u64*)(pA + g * 32 * PS + i * PS + j4 + 2));
                ADD2(ao01,  ao01,  *(const u64*)(pO + g * 32 * PS + i * PS + j4));
                ADD2(ao23,  ao23,  *(const u64*)(pO + g * 32 * PS + i * PS + j4 + 2));
            }
            *(u64*)(uish + i * PS + j4)     = aui01;
            *(u64*)(uish + i * PS + j4 + 2) = aui23;
        }
        __syncthreads();                                   // C
        if (h == 0) {
            // o = ao + attn @ ui
#pragma unroll
            for (int c4 = 0; c4 < 8; c4++) {
                float4 a4 = *(const float4*)(a + i * PS + c4 * 4);
#define ASTEP(m, ac)                                                            \
                {                                                               \
                    ulonglong2 uu = *(const ulonglong2*)(uish + (c4*4 + m) * PS + j4); \
                    u64 a2; PK2(a2, ac, ac);                                    \
                    FMA2(ao01, a2, uu.x, ao01); FMA2(ao23, a2, uu.y, ao23);     \
                }
                ASTEP(0, a4.x) ASTEP(1, a4.y) ASTEP(2, a4.z) ASTEP(3, a4.w)
#undef ASTEP
            }
            ulonglong2 ov; ov.x = ao01; ov.y = ao23;
            *(ulonglong2*)(out + ((size_t)bh * 4096 + n * 32 + i) * 128 + sl * 32 + j4) = ov;
        }

        // S += kn^T @ ui  (all 1024 threads; 2 rows x 2 cols each)
        {
            u64 s0 = *(const u64*)(S + (ur0 + 0) * PS + uj2);
            u64 s1 = *(const u64*)(S + (ur0 + 1) * PS + uj2);
#pragma unroll 4
            for (int c = 0; c < 32; c++) {
                float2 k2v = *(const float2*)(k + c * PW + ur0);
                u64 uu = *(const u64*)(uish + c * PS + uj2);
                u64 k02, k12;
                PK2(k02, k2v.x, k2v.x); PK2(k12, k2v.y, k2v.y);
                FMA2(s0, k02, uu, s0);
                FMA2(s1, k12, uu, s1);
            }
            *(u64*)(S + (ur0 + 0) * PS + uj2) = s0;
            *(u64*)(S + (ur0 + 1) * PS + uj2) = s1;
        }
    }
    __syncthreads();

    // final state S -> second output tensor (b,h,dk,dv)
    if (out_size >= OUT_ELEMS + S_ELEMS) {
        int ii = tid >> 3;                  // 0..127
        int jj4 = (tid & 7) << 2;
        *(ulonglong2*)(out + OUT_ELEMS + ((size_t)bh * 128 + ii) * 128 + sl * 32 + jj4) =
            *(const ulonglong2*)(S + ii * PS + jj4);
    }
}

// ---------------------------------------------------------------------------
extern "C" void kernel_launch(void* const* d_in, const int* in_sizes, int n_in,
                              void* d_out, int out_size) {
    const float* q    = (const float*)d_in[0];
    const float* k    = (const float*)d_in[1];
    const float* v    = (const float*)d_in[2];
    const float* beta = (const float*)d_in[3];
    float* out = (float*)d_out;

    const int k1_smem = (3 * 32 * PW + 4 * 1024 + 64) * 4;                       // 67,456 B
    const int k2_smem = (128 * PS + 7 * 32 * PS + 2 * BUF_FLOATS) * 4;           // 170,496 B

    cudaFuncSetAttribute(k1_kernel, cudaFuncAttributeMaxDynamicSharedMemorySize, k1_smem);
    cudaFuncSetAttribute(k2_kernel, cudaFuncAttributeMaxDynamicSharedMemorySize, k2_smem);

    k1_kernel<<<NTILES, 256, k1_smem>>>(q, k, v, beta);
    k2_kernel<<<dim3(4, 16, 2), 1024, k2_smem>>>(out, out_size);
}

// round 14
// speedup vs baseline: 1.2174x; 1.2174x over previous
#include <cuda_runtime.h>
#include <cstdint>

// Problem constants: b=2, h=16, L=4096, d=128, chunk=32
#define NTILES   4096
#define OUT_ELEMS 16777216
#define S_ELEMS   524288
#define PW 132                   // padded stride for 128-wide rows
#define PS 36                    // padded stride for 32-wide rows

typedef unsigned long long u64;

// Scratch (static device globals). g_w holds NEGATED w.
__device__ float g_qn[16777216];
__device__ float g_kn[16777216];
__device__ float g_w [16777216];
__device__ float g_u [16777216];
__device__ float g_attn[4194304];

#define FMA2(d, a, b, c) asm("fma.rn.f32x2 %0, %1, %2, %3;" : "=l"(d) : "l"(a), "l"(b), "l"(c))
#define ADD2(d, a, b)    asm("add.rn.f32x2 %0, %1, %2;"     : "=l"(d) : "l"(a), "l"(b))
#define PK2(d, lo, hi)   asm("mov.b64 %0, {%1, %2};"        : "=l"(d) : "f"(lo), "f"(hi))
#define UPK2(lo, hi, s)  asm("mov.b64 {%0, %1}, %2;"        : "=f"(lo), "=f"(hi) : "l"(s))

__device__ __forceinline__ void cpa16(float* dst_smem, const float* src_gmem) {
    uint32_t d = (uint32_t)__cvta_generic_to_shared(dst_smem);
    asm volatile("cp.async.cg.shared.global [%0], [%1], 16;\n" :: "r"(d), "l"(src_gmem));
}
#define CP_COMMIT() asm volatile("cp.async.commit_group;\n" ::: "memory")
#define CP_WAIT0()  asm volatile("cp.async.wait_group 0;\n" ::: "memory")

// 32x32 matmul on shared (stride-32): out = (adds? adds:0) + a @ b   (f32x2)
__device__ __forceinline__ void mm32(float* __restrict__ out,
                                     const float* __restrict__ a,
                                     const float* __restrict__ b,
                                     const float* __restrict__ adds,
                                     int tid) {
    int i  = tid >> 3;
    int j4 = (tid & 7) << 2;
    float ar[32];
#pragma unroll
    for (int c = 0; c < 8; c++) {
        float4 t = *(const float4*)(a + i * 32 + c * 4);
        ar[c*4+0] = t.x; ar[c*4+1] = t.y; ar[c*4+2] = t.z; ar[c*4+3] = t.w;
    }
    u64 acc01 = 0, acc23 = 0;
    if (adds) {
        ulonglong2 ad = *(const ulonglong2*)(adds + i * 32 + j4);
        acc01 = ad.x; acc23 = ad.y;
    }
#pragma unroll
    for (int kk = 0; kk < 32; kk++) {
        ulonglong2 b2 = *(const ulonglong2*)(b + kk * 32 + j4);
        u64 a2; PK2(a2, ar[kk], ar[kk]);
        FMA2(acc01, a2, b2.x, acc01);
        FMA2(acc23, a2, b2.y, acc23);
    }
    ulonglong2 o; o.x = acc01; o.y = acc23;
    *(ulonglong2*)(out + i * 32 + j4) = o;
}

// ---------------------------------------------------------------------------
// Kernel 1: per chunk-tile (4096 CTAs). (round-6 version, unchanged)
// ---------------------------------------------------------------------------
extern __shared__ float sm1[];

__global__ void __launch_bounds__(256, 3)
k1_kernel(const float* __restrict__ q, const float* __restrict__ k,
          const float* __restrict__ v, const float* __restrict__ beta) {
    float* qn   = sm1;               // 32*PW
    float* kn   = qn + 32 * PW;      // 32*PW
    float* vbkt = kn + 32 * PW;      // 32*PW  (kt first, vb later)
    float* Am = vbkt + 32 * PW;      // 1024
    float* Bm = Am + 1024;
    float* Xm = Bm + 1024;
    float* Ym = Xm + 1024;
    float* beta_s  = Ym + 1024;      // 32
    float* nbeta_s = beta_s + 32;    // 32

    const int tid  = threadIdx.x;
    const int tile = blockIdx.x;
    const size_t base = (size_t)tile * 4096;
    const int brow = tile * 32;

    {
        int wp = tid >> 5, lane = tid & 31;
#pragma unroll
        for (int rr = 0; rr < 4; rr++) {
            int r = wp * 4 + rr;
            float4 a = *(const float4*)(q + base + r * 128 + lane * 4);
            float s = a.x*a.x + a.y*a.y + a.z*a.z + a.w*a.w;
#pragma unroll
            for (int off = 16; off; off >>= 1) s += __shfl_xor_sync(0xffffffffu, s, off);
            float sc = rsqrtf(s + 1e-6f);
            float4 o = make_float4(a.x*sc, a.y*sc, a.z*sc, a.w*sc);
            *(float4*)(qn + r * PW + lane * 4) = o;
            *(float4*)(g_qn + base + r * 128 + lane * 4) = o;

            float4 b = *(const float4*)(k + base + r * 128 + lane * 4);
            float sk = b.x*b.x + b.y*b.y + b.z*b.z + b.w*b.w;
#pragma unroll
            for (int off = 16; off; off >>= 1) sk += __shfl_xor_sync(0xffffffffu, sk, off);
            float sck = rsqrtf(sk + 1e-6f);
            float4 ok = make_float4(b.x*sck, b.y*sck, b.z*sck, b.w*sck);
            *(float4*)(kn + r * PW + lane * 4) = ok;
            *(float4*)(g_kn + base + r * 128 + lane * 4) = ok;
        }
        if (tid < 32) {
            float b = beta[brow + tid];
            beta_s[tid] = b;
            nbeta_s[tid] = -b;
        }
    }
    __syncthreads();

    // kt (128 x 32) into vbkt
    {
#pragma unroll
        for (int t = 0; t < 4; t++) {
            int idx = tid + t * 256;
            int r = idx & 31, g = idx >> 5;
            float4 f = *(const float4*)(kn + r * PW + g * 4);
            vbkt[(4*g+0) * 32 + r] = f.x;
            vbkt[(4*g+1) * 32 + r] = f.y;
            vbkt[(4*g+2) * 32 + r] = f.z;
            vbkt[(4*g+3) * 32 + r] = f.w;
        }
    }
    __syncthreads();

    // T0/attn
    {
        const float* kt = vbkt;
        const int h  = tid >> 7;
        const int t  = tid & 127;
        const int r0 = (t >> 3) * 2, r1 = r0 + 1;
        const int j4 = (t & 7) << 2;
        u64 aK0a=0,aK0b=0,aK1a=0,aK1b=0, aQ0a=0,aQ0b=0,aQ1a=0,aQ1b=0;
        const int c0 = h * 64;
#pragma unroll 4
        for (int c = c0; c < c0 + 64; c++) {
            ulonglong2 kt2 = *(const ulonglong2*)(kt + c * 32 + j4);
            float k0v = kn[r0*PW + c], k1v = kn[r1*PW + c];
            float q0v = qn[r0*PW + c], q1v = qn[r1*PW + c];
            u64 k02,k12,q02,q12;
            PK2(k02,k0v,k0v); PK2(k12,k1v,k1v); PK2(q02,q0v,q0v); PK2(q12,q1v,q1v);
            FMA2(aK0a,k02,kt2.x,aK0a); FMA2(aK0b,k02,kt2.y,aK0b);
            FMA2(aK1a,k12,kt2.x,aK1a); FMA2(aK1b,k12,kt2.y,aK1b);
            FMA2(aQ0a,q02,kt2.x,aQ0a); FMA2(aQ0b,q02,kt2.y,aQ0b);
            FMA2(aQ1a,q12,kt2.x,aQ1a); FMA2(aQ1b,q12,kt2.y,aQ1b);
        }
        if (h == 1) {
            *(u64*)(Bm + r0*32 + j4)   = aK0a; *(u64*)(Bm + r0*32 + j4+2) = aK0b;
            *(u64*)(Bm + r1*32 + j4)   = aK1a; *(u64*)(Bm + r1*32 + j4+2) = aK1b;
            *(u64*)(Ym + r0*32 + j4)   = aQ0a; *(u64*)(Ym + r0*32 + j4+2) = aQ0b;
            *(u64*)(Ym + r1*32 + j4)   = aQ1a; *(u64*)(Ym + r1*32 + j4+2) = aQ1b;
        }
        __syncthreads();
        if (h == 0) {
            ADD2(aK0a, aK0a, *(const u64*)(Bm + r0*32 + j4));
            ADD2(aK0b, aK0b, *(const u64*)(Bm + r0*32 + j4+2));
            ADD2(aK1a, aK1a, *(const u64*)(Bm + r1*32 + j4));
            ADD2(aK1b, aK1b, *(const u64*)(Bm + r1*32 + j4+2));
            ADD2(aQ0a, aQ0a, *(const u64*)(Ym + r0*32 + j4));
            ADD2(aQ0b, aQ0b, *(const u64*)(Ym + r0*32 + j4+2));
            ADD2(aQ1a, aQ1a, *(const u64*)(Ym + r1*32 + j4));
            ADD2(aQ1b, aQ1b, *(const u64*)(Ym + r1*32 + j4+2));
            float K0[4], K1[4], Q0[4], Q1[4];
            UPK2(K0[0],K0[1],aK0a); UPK2(K0[2],K0[3],aK0b);
            UPK2(K1[0],K1[1],aK1a); UPK2(K1[2],K1[3],aK1b);
            UPK2(Q0[0],Q0[1],aQ0a); UPK2(Q0[2],Q0[3],aQ0b);
            UPK2(Q1[0],Q1[1],aQ1a); UPK2(Q1[2],Q1[3],aQ1b);
#pragma unroll
            for (int rr = 0; rr < 2; rr++) {
                int row = r0 + rr;
                const float* K = rr ? K1 : K0;
                const float* Q = rr ? Q1 : Q0;
                float bb = beta_s[row];
                float att[4];
#pragma unroll
                for (int m = 0; m < 4; m++) {
                    int j = j4 + m;
                    float t0 = (row > j) ? (-bb * K[m]) : 0.f;
                    Am[row*32 + j] = t0;
                    Xm[row*32 + j] = t0 + ((row == j) ? 1.f : 0.f);
                    att[m] = (row >= j) ? Q[m] : 0.f;
                }
                *(float4*)(g_attn + (size_t)tile * 1024 + row * 32 + j4) =
                    make_float4(att[0], att[1], att[2], att[3]);
            }
        }
        __syncthreads();
    }

    // (I - T0)^{-1} via nilpotent squaring
    float *Ap = Am, *Bp = Bm, *Xp = Xm, *Yp = Ym;
#pragma unroll 1
    for (int s = 0; s < 4; s++) {
        mm32(Bp, Ap, Ap, nullptr, tid);
        __syncthreads();
        mm32(Yp, Xp, Bp, Xp, tid);
        __syncthreads();
        float* t;
        t = Ap; Ap = Bp; Bp = t;
        t = Xp; Xp = Yp; Yp = t;
    }

    // vb = v * beta
    for (int x = tid; x < 1024; x += 256) {
        int r = x >> 5, c4 = (x & 31) << 2;
        float4 vv = *(const float4*)(v + base + r * 128 + c4);
        float bb = beta_s[r];
        *(float4*)(vbkt + r * PW + c4) = make_float4(vv.x*bb, vv.y*bb, vv.z*bb, vv.w*bb);
    }
    __syncthreads();

    // g_w = -(Xp @ (kn * beta)), g_u = Xp @ vb
    {
        int i  = tid >> 3;
        int jg = tid & 7;
        float xr[32];
#pragma unroll
        for (int c = 0; c < 8; c++) {
            float4 t = *(const float4*)(Xp + i * 32 + c * 4);
            xr[c*4+0] = t.x; xr[c*4+1] = t.y; xr[c*4+2] = t.z; xr[c*4+3] = t.w;
        }

#pragma unroll 1
        for (int cblk = 0; cblk < 4; cblk++) {
            int c = cblk * 32 + jg * 4;
            u64 w01 = 0, w23 = 0, u01 = 0, u23 = 0;
#pragma unroll
            for (int kk = 0; kk < 32; kk++) {
                ulonglong2 k2v = *(const ulonglong2*)(kn   + kk * PW + c);
                ulonglong2 v2v = *(const ulonglong2*)(vbkt + kk * PW + c);
                float xbv = xr[kk] * nbeta_s[kk];
                u64 xb2, xr2;
                PK2(xb2, xbv, xbv); PK2(xr2, xr[kk], xr[kk]);
                FMA2(w01, xb2, k2v.x, w01); FMA2(w23, xb2, k2v.y, w23);
                FMA2(u01, xr2, v2v.x, u01); FMA2(u23, xr2, v2v.y, u23);
            }
            ulonglong2 ow; ow.x = w01; ow.y = w23;
            ulonglong2 ou; ou.x = u01; ou.y = u23;
            *(ulonglong2*)(g_w + base + i * 128 + c) = ow;
            *(ulonglong2*)(g_u + base + i * 128 + c) = ou;
        }
    }
}

// ---------------------------------------------------------------------------
// Kernel 2: sequential scan, 512 threads, K-split QUARTERS, 2-row blocking:
// each thread computes rows (r, r+16) x 4 cols over K=32 -> S smem traffic
// halves vs round-3. 256-thread combine + epilogue. 3 barriers/chunk.
// ---------------------------------------------------------------------------
#define BUF_FLOATS (3 * 32 * PW + 2 * 32 * PS)   // 12672 + 2304 = 14976

extern __shared__ float sm2[];

__device__ __forceinline__ void k2_prefetch(int n, float* buf, int bh, int sl, int tid) {
    const size_t tb = ((size_t)bh * 128 + n) * 4096;
    float* w = buf;
    float* q = buf + 32 * PW;
    float* k = buf + 64 * PW;
    float* u = buf + 96 * PW;
    float* a = buf + 96 * PW + 32 * PS;
#pragma unroll
    for (int t = 0; t < 2; t++) {
        int idx = tid + t * 512;               // 0..1023
        int r = idx >> 5, c4 = (idx & 31) << 2;
        cpa16(w + r * PW + c4, g_w  + tb + r * 128 + c4);
        cpa16(q + r * PW + c4, g_qn + tb + r * 128 + c4);
        cpa16(k + r * PW + c4, g_kn + tb + r * 128 + c4);
    }
    if (tid < 256) {
        int r = tid >> 3, c4 = (tid & 7) << 2;
        cpa16(u + r * PS + c4, g_u + tb + r * 128 + sl * 32 + c4);
    } else {
        int t2 = tid - 256;
        int r = t2 >> 3, c4 = (t2 & 7) << 2;
        cpa16(a + r * PS + c4, g_attn + ((size_t)bh * 128 + n) * 1024 + r * 32 + c4);
    }
}

__global__ void __launch_bounds__(512, 1)
k2_kernel(float* __restrict__ out, int out_size) {
    float* S    = sm2;                        // 128*PS = 4608
    float* uish = S + 128 * PS;               // 32*PS
    float* pA   = uish + 32 * PS;             // 4 * 32*PS
    float* pO   = pA + 4 * 32 * PS;           // 4 * 32*PS
    float* bufs = pO + 4 * 32 * PS;           // 2*BUF_FLOATS

    const int tid = threadIdx.x;
    const int sl  = blockIdx.x;
    const int bh  = blockIdx.z * 16 + blockIdx.y;
    // main-loop mapping: quarter h, 16 row-pairs x 8 col groups
    const int h   = tid >> 7;                 // K-quarter 0..3
    const int t7  = tid & 127;
    const int r0  = t7 >> 3;                  // 0..15
    const int r1  = r0 + 16;
    const int j4  = (t7 & 7) << 2;
    const int kb  = h * 32;                   // K base for this quarter
    // combine/epilogue mapping (tid < 256)
    const int ci  = tid >> 3;                 // 0..31
    const int cj4 = (tid & 7) << 2;
    // update mapping (all 512): 4 contig rows x 2 cols
    const int ur0 = (tid >> 4) << 2;
    const int uj2 = (tid & 15) << 1;

    for (int x = tid; x < 128 * PS; x += 512) S[x] = 0.f;

    k2_prefetch(0, bufs, bh, sl, tid);
    CP_COMMIT();

#pragma unroll 1
    for (int n = 0; n < 128; n++) {
        float* buf = bufs + (n & 1) * BUF_FLOATS;
        CP_WAIT0();
        __syncthreads();                                   // A
        if (n + 1 < 128) { k2_prefetch(n + 1, bufs + ((n + 1) & 1) * BUF_FLOATS, bh, sl, tid); CP_COMMIT(); }

        const float* w = buf;
        const float* q = buf + 32 * PW;
        const float* k = buf + 64 * PW;
        const float* u = buf + 96 * PW;
        const float* a = buf + 96 * PW + 32 * PS;

        // main: 2 rows x 4 cols per thread over this quarter's K=32
        u64 A0a = 0, A0b = 0, O0a = 0, O0b = 0;
        u64 A1a = 0, A1b = 0, O1a = 0, O1b = 0;
#pragma unroll 2
        for (int kk4 = 0; kk4 < 8; kk4++) {
            float4 w40 = *(const float4*)(w + r0 * PW + kb + kk4 * 4);
            float4 w41 = *(const float4*)(w + r1 * PW + kb + kk4 * 4);
            float4 q40 = *(const float4*)(q + r0 * PW + kb + kk4 * 4);
            float4 q41 = *(const float4*)(q + r1 * PW + kb + kk4 * 4);
#define MSTEP(m, w0c, w1c, q0c, q1c)                                            \
            {                                                                   \
                ulonglong2 s2 = *(const ulonglong2*)(S + (kb + kk4*4 + m) * PS + j4); \
                u64 w0p, w1p, q0p, q1p;                                         \
                PK2(w0p, w0c, w0c); PK2(w1p, w1c, w1c);                         \
                PK2(q0p, q0c, q0c); PK2(q1p, q1c, q1c);                         \
                FMA2(A0a, w0p, s2.x, A0a); FMA2(A0b, w0p, s2.y, A0b);           \
                FMA2(O0a, q0p, s2.x, O0a); FMA2(O0b, q0p, s2.y, O0b);           \
                FMA2(A1a, w1p, s2.x, A1a); FMA2(A1b, w1p, s2.y, A1b);           \
                FMA2(O1a, q1p, s2.x, O1a); FMA2(O1b, q1p, s2.y, O1b);           \
            }
            MSTEP(0, w40.x, w41.x, q40.x, q41.x)
            MSTEP(1, w40.y, w41.y, q40.y, q41.y)
            MSTEP(2, w40.z, w41.z, q40.z, q41.z)
            MSTEP(3, w40.w, w41.w, q40.w, q41.w)
#undef MSTEP
        }
        // publish partials (all threads, group h)
        {
            float* gA = pA + h * 32 * PS;
            float* gO = pO + h * 32 * PS;
            *(u64*)(gA + r0 * PS + j4)     = A0a;
            *(u64*)(gA + r0 * PS + j4 + 2) = A0b;
            *(u64*)(gA + r1 * PS + j4)     = A1a;
            *(u64*)(gA + r1 * PS + j4 + 2) = A1b;
            *(u64*)(gO + r0 * PS + j4)     = O0a;
            *(u64*)(gO + r0 * PS + j4 + 2) = O0b;
            *(u64*)(gO + r1 * PS + j4)     = O1a;
            *(u64*)(gO + r1 * PS + j4 + 2) = O1b;
        }
        __syncthreads();                                   // B
        u64 ao01 = 0, ao23 = 0;
        if (tid < 256) {
            ulonglong2 t = *(const ulonglong2*)(u + ci * PS + cj4);
            u64 aui01 = t.x, aui23 = t.y;
#pragma unroll
            for (int g = 0; g < 4; g++) {
                ADD2(aui01, aui01, *(const u64*)(pA + g * 32 * PS + ci * PS + cj4));
                ADD2(aui23, aui23, *(const u64*)(pA + g * 32 * PS + ci * PS + cj4 + 2));
                ADD2(ao01,  ao01,  *(const u64*)(pO + g * 32 * PS + ci * PS + cj4));
                ADD2(ao23,  ao23,  *(const u64*)(pO + g * 32 * PS + ci * PS + cj4 + 2));
            }
            *(u64*)(uish + ci * PS + cj4)     = aui01;
            *(u64*)(uish + ci * PS + cj4 + 2) = aui23;
        }
        __syncthreads();                                   // C
        if (tid < 256) {
            // o = ao + attn @ ui
#pragma unroll
            for (int c4 = 0; c4 < 8; c4++) {
                float4 a4 = *(const float4*)(a + ci * PS + c4 * 4);
#define ASTEP(m, ac)                                                            \
                {                                                               \
                    ulonglong2 uu = *(const ulonglong2*)(uish + (c4*4 + m) * PS + cj4); \
                    u64 a2; PK2(a2, ac, ac);                                    \
                    FMA2(ao01, a2, uu.x, ao01); FMA2(ao23, a2, uu.y, ao23);     \
                }
                ASTEP(0, a4.x) ASTEP(1, a4.y) ASTEP(2, a4.z) ASTEP(3, a4.w)
#undef ASTEP
            }
            ulonglong2 ov; ov.x = ao01; ov.y = ao23;
            *(ulonglong2*)(out + ((size_t)bh * 4096 + n * 32 + ci) * 128 + sl * 32 + cj4) = ov;
        }

        // S += kn^T @ ui  (all 512 threads; 4 contig rows x 2 cols each)
        {
            u64 s0 = *(const u64*)(S + (ur0 + 0) * PS + uj2);
            u64 s1 = *(const u64*)(S + (ur0 + 1) * PS + uj2);
            u64 s2v = *(const u64*)(S + (ur0 + 2) * PS + uj2);
            u64 s3 = *(const u64*)(S + (ur0 + 3) * PS + uj2);
#pragma unroll 4
            for (int c = 0; c < 32; c++) {
                float4 k4 = *(const float4*)(k + c * PW + ur0);
                u64 uu = *(const u64*)(uish + c * PS + uj2);
                u64 k02, k12, k22, k32;
                PK2(k02, k4.x, k4.x); PK2(k12, k4.y, k4.y);
                PK2(k22, k4.z, k4.z); PK2(k32, k4.w, k4.w);
                FMA2(s0, k02, uu, s0);
                FMA2(s1, k12, uu, s1);
                FMA2(s2v, k22, uu, s2v);
                FMA2(s3, k32, uu, s3);
            }
            *(u64*)(S + (ur0 + 0) * PS + uj2) = s0;
            *(u64*)(S + (ur0 + 1) * PS + uj2) = s1;
            *(u64*)(S + (ur0 + 2) * PS + uj2) = s2v;
            *(u64*)(S + (ur0 + 3) * PS + uj2) = s3;
        }
    }
    __syncthreads();

    // final state S -> second output tensor (b,h,dk,dv)
    if (out_size >= OUT_ELEMS + S_ELEMS) {
        int ii = tid >> 3;                  // 0..63
        int jj4 = (tid & 7) << 2;
#pragma unroll
        for (int rb = 0; rb < 2; rb++) {
            int kd = ii + rb * 64;
            *(ulonglong2*)(out + OUT_ELEMS + ((size_t)bh * 128 + kd) * 128 + sl * 32 + jj4) =
                *(const ulonglong2*)(S + kd * PS + jj4);
        }
    }
}

// ---------------------------------------------------------------------------
extern "C" void kernel_launch(void* const* d_in, const int* in_sizes, int n_in,
                              void* d_out, int out_size) {
    const float* q    = (const float*)d_in[0];
    const float* k    = (const float*)d_in[1];
    const float* v    = (const float*)d_in[2];
    const float* beta = (const float*)d_in[3];
    float* out = (float*)d_out;

    const int k1_smem = (3 * 32 * PW + 4 * 1024 + 64) * 4;                       // 67,456 B
    const int k2_smem = (128 * PS + 9 * 32 * PS + 2 * BUF_FLOATS) * 4;           // 179,712 B

    cudaFuncSetAttribute(k1_kernel, cudaFuncAttributeMaxDynamicSharedMemorySize, k1_smem);
    cudaFuncSetAttribute(k2_kernel, cudaFuncAttributeMaxDynamicSharedMemorySize, k2_smem);

    k1_kernel<<<NTILES, 256, k1_smem>>>(q, k, v, beta);
    k2_kernel<<<dim3(4, 16, 2), 512, k2_smem>>>(out, out_size);
}

// round 15
// speedup vs baseline: 1.2322x; 1.0122x over previous
#include <cuda_runtime.h>
#include <cstdint>

// Problem constants: b=2, h=16, L=4096, d=128, chunk=32
#define NTILES   4096
#define OUT_ELEMS 16777216
#define S_ELEMS   524288
#define PW 132                   // padded stride for 128-wide rows
#define PS 36                    // padded stride for 32-wide rows

typedef unsigned long long u64;

// Scratch (static device globals). g_w holds NEGATED w.
__device__ float g_qn[16777216];
__device__ float g_kn[16777216];
__device__ float g_w [16777216];
__device__ float g_u [16777216];
__device__ float g_attn[4194304];

#define FMA2(d, a, b, c) asm("fma.rn.f32x2 %0, %1, %2, %3;" : "=l"(d) : "l"(a), "l"(b), "l"(c))
#define ADD2(d, a, b)    asm("add.rn.f32x2 %0, %1, %2;"     : "=l"(d) : "l"(a), "l"(b))
#define PK2(d, lo, hi)   asm("mov.b64 %0, {%1, %2};"        : "=l"(d) : "f"(lo), "f"(hi))
#define UPK2(lo, hi, s)  asm("mov.b64 {%0, %1}, %2;"        : "=f"(lo), "=f"(hi) : "l"(s))

__device__ __forceinline__ void cpa16(float* dst_smem, const float* src_gmem) {
    uint32_t d = (uint32_t)__cvta_generic_to_shared(dst_smem);
    asm volatile("cp.async.cg.shared.global [%0], [%1], 16;\n" :: "r"(d), "l"(src_gmem));
}
#define CP_COMMIT() asm volatile("cp.async.commit_group;\n" ::: "memory")
#define CP_WAIT0()  asm volatile("cp.async.wait_group 0;\n" ::: "memory")

// 32x32 matmul on shared (stride-32): out = (adds? adds:0) + a @ b   (f32x2)
__device__ __forceinline__ void mm32(float* __restrict__ out,
                                     const float* __restrict__ a,
                                     const float* __restrict__ b,
                                     const float* __restrict__ adds,
                                     int tid) {
    int i  = tid >> 3;
    int j4 = (tid & 7) << 2;
    float ar[32];
#pragma unroll
    for (int c = 0; c < 8; c++) {
        float4 t = *(const float4*)(a + i * 32 + c * 4);
        ar[c*4+0] = t.x; ar[c*4+1] = t.y; ar[c*4+2] = t.z; ar[c*4+3] = t.w;
    }
    u64 acc01 = 0, acc23 = 0;
    if (adds) {
        ulonglong2 ad = *(const ulonglong2*)(adds + i * 32 + j4);
        acc01 = ad.x; acc23 = ad.y;
    }
#pragma unroll
    for (int kk = 0; kk < 32; kk++) {
        ulonglong2 b2 = *(const ulonglong2*)(b + kk * 32 + j4);
        u64 a2; PK2(a2, ar[kk], ar[kk]);
        FMA2(acc01, a2, b2.x, acc01);
        FMA2(acc23, a2, b2.y, acc23);
    }
    ulonglong2 o; o.x = acc01; o.y = acc23;
    *(ulonglong2*)(out + i * 32 + j4) = o;
}

// ---------------------------------------------------------------------------
// Kernel 1: per chunk-tile (4096 CTAs). (unchanged)
// ---------------------------------------------------------------------------
extern __shared__ float sm1[];

__global__ void __launch_bounds__(256, 3)
k1_kernel(const float* __restrict__ q, const float* __restrict__ k,
          const float* __restrict__ v, const float* __restrict__ beta) {
    float* qn   = sm1;               // 32*PW
    float* kn   = qn + 32 * PW;      // 32*PW
    float* vbkt = kn + 32 * PW;      // 32*PW  (kt first, vb later)
    float* Am = vbkt + 32 * PW;      // 1024
    float* Bm = Am + 1024;
    float* Xm = Bm + 1024;
    float* Ym = Xm + 1024;
    float* beta_s  = Ym + 1024;      // 32
    float* nbeta_s = beta_s + 32;    // 32

    const int tid  = threadIdx.x;
    const int tile = blockIdx.x;
    const size_t base = (size_t)tile * 4096;
    const int brow = tile * 32;

    {
        int wp = tid >> 5, lane = tid & 31;
#pragma unroll
        for (int rr = 0; rr < 4; rr++) {
            int r = wp * 4 + rr;
            float4 a = *(const float4*)(q + base + r * 128 + lane * 4);
            float s = a.x*a.x + a.y*a.y + a.z*a.z + a.w*a.w;
#pragma unroll
            for (int off = 16; off; off >>= 1) s += __shfl_xor_sync(0xffffffffu, s, off);
            float sc = rsqrtf(s + 1e-6f);
            float4 o = make_float4(a.x*sc, a.y*sc, a.z*sc, a.w*sc);
            *(float4*)(qn + r * PW + lane * 4) = o;
            *(float4*)(g_qn + base + r * 128 + lane * 4) = o;

            float4 b = *(const float4*)(k + base + r * 128 + lane * 4);
            float sk = b.x*b.x + b.y*b.y + b.z*b.z + b.w*b.w;
#pragma unroll
            for (int off = 16; off; off >>= 1) sk += __shfl_xor_sync(0xffffffffu, sk, off);
            float sck = rsqrtf(sk + 1e-6f);
            float4 ok = make_float4(b.x*sck, b.y*sck, b.z*sck, b.w*sck);
            *(float4*)(kn + r * PW + lane * 4) = ok;
            *(float4*)(g_kn + base + r * 128 + lane * 4) = ok;
        }
        if (tid < 32) {
            float b = beta[brow + tid];
            beta_s[tid] = b;
            nbeta_s[tid] = -b;
        }
    }
    __syncthreads();

    // kt (128 x 32) into vbkt
    {
#pragma unroll
        for (int t = 0; t < 4; t++) {
            int idx = tid + t * 256;
            int r = idx & 31, g = idx >> 5;
            float4 f = *(const float4*)(kn + r * PW + g * 4);
            vbkt[(4*g+0) * 32 + r] = f.x;
            vbkt[(4*g+1) * 32 + r] = f.y;
            vbkt[(4*g+2) * 32 + r] = f.z;
            vbkt[(4*g+3) * 32 + r] = f.w;
        }
    }
    __syncthreads();

    // T0/attn
    {
        const float* kt = vbkt;
        const int h  = tid >> 7;
        const int t  = tid & 127;
        const int r0 = (t >> 3) * 2, r1 = r0 + 1;
        const int j4 = (t & 7) << 2;
        u64 aK0a=0,aK0b=0,aK1a=0,aK1b=0, aQ0a=0,aQ0b=0,aQ1a=0,aQ1b=0;
        const int c0 = h * 64;
#pragma unroll 4
        for (int c = c0; c < c0 + 64; c++) {
            ulonglong2 kt2 = *(const ulonglong2*)(kt + c * 32 + j4);
            float k0v = kn[r0*PW + c], k1v = kn[r1*PW + c];
            float q0v = qn[r0*PW + c], q1v = qn[r1*PW + c];
            u64 k02,k12,q02,q12;
            PK2(k02,k0v,k0v); PK2(k12,k1v,k1v); PK2(q02,q0v,q0v); PK2(q12,q1v,q1v);
            FMA2(aK0a,k02,kt2.x,aK0a); FMA2(aK0b,k02,kt2.y,aK0b);
            FMA2(aK1a,k12,kt2.x,aK1a); FMA2(aK1b,k12,kt2.y,aK1b);
            FMA2(aQ0a,q02,kt2.x,aQ0a); FMA2(aQ0b,q02,kt2.y,aQ0b);
            FMA2(aQ1a,q12,kt2.x,aQ1a); FMA2(aQ1b,q12,kt2.y,aQ1b);
        }
        if (h == 1) {
            *(u64*)(Bm + r0*32 + j4)   = aK0a; *(u64*)(Bm + r0*32 + j4+2) = aK0b;
            *(u64*)(Bm + r1*32 + j4)   = aK1a; *(u64*)(Bm + r1*32 + j4+2) = aK1b;
            *(u64*)(Ym + r0*32 + j4)   = aQ0a; *(u64*)(Ym + r0*32 + j4+2) = aQ0b;
            *(u64*)(Ym + r1*32 + j4)   = aQ1a; *(u64*)(Ym + r1*32 + j4+2) = aQ1b;
        }
        __syncthreads();
        if (h == 0) {
            ADD2(aK0a, aK0a, *(const u64*)(Bm + r0*32 + j4));
            ADD2(aK0b, aK0b, *(const u64*)(Bm + r0*32 + j4+2));
            ADD2(aK1a, aK1a, *(const u64*)(Bm + r1*32 + j4));
            ADD2(aK1b, aK1b, *(const u64*)(Bm + r1*32 + j4+2));
            ADD2(aQ0a, aQ0a, *(const u64*)(Ym + r0*32 + j4));
            ADD2(aQ0b, aQ0b, *(const u64*)(Ym + r0*32 + j4+2));
            ADD2(aQ1a, aQ1a, *(const u64*)(Ym + r1*32 + j4));
            ADD2(aQ1b, aQ1b, *(const u64*)(Ym + r1*32 + j4+2));
            float K0[4], K1[4], Q0[4], Q1[4];
            UPK2(K0[0],K0[1],aK0a); UPK2(K0[2],K0[3],aK0b);
            UPK2(K1[0],K1[1],aK1a); UPK2(K1[2],K1[3],aK1b);
            UPK2(Q0[0],Q0[1],aQ0a); UPK2(Q0[2],Q0[3],aQ0b);
            UPK2(Q1[0],Q1[1],aQ1a); UPK2(Q1[2],Q1[3],aQ1b);
#pragma unroll
            for (int rr = 0; rr < 2; rr++) {
                int row = r0 + rr;
                const float* K = rr ? K1 : K0;
                const float* Q = rr ? Q1 : Q0;
                float bb = beta_s[row];
                float att[4];
#pragma unroll
                for (int m = 0; m < 4; m++) {
                    int j = j4 + m;
                    float t0 = (row > j) ? (-bb * K[m]) : 0.f;
                    Am[row*32 + j] = t0;
                    Xm[row*32 + j] = t0 + ((row == j) ? 1.f : 0.f);
                    att[m] = (row >= j) ? Q[m] : 0.f;
                }
                *(float4*)(g_attn + (size_t)tile * 1024 + row * 32 + j4) =
                    make_float4(att[0], att[1], att[2], att[3]);
            }
        }
        __syncthreads();
    }

    // (I - T0)^{-1} via nilpotent squaring
    float *Ap = Am, *Bp = Bm, *Xp = Xm, *Yp = Ym;
#pragma unroll 1
    for (int s = 0; s < 4; s++) {
        mm32(Bp, Ap, Ap, nullptr, tid);
        __syncthreads();
        mm32(Yp, Xp, Bp, Xp, tid);
        __syncthreads();
        float* t;
        t = Ap; Ap = Bp; Bp = t;
        t = Xp; Xp = Yp; Yp = t;
    }

    // vb = v * beta
    for (int x = tid; x < 1024; x += 256) {
        int r = x >> 5, c4 = (x & 31) << 2;
        float4 vv = *(const float4*)(v + base + r * 128 + c4);
        float bb = beta_s[r];
        *(float4*)(vbkt + r * PW + c4) = make_float4(vv.x*bb, vv.y*bb, vv.z*bb, vv.w*bb);
    }
    __syncthreads();

    // g_w = -(Xp @ (kn * beta)), g_u = Xp @ vb
    {
        int i  = tid >> 3;
        int jg = tid & 7;
        float xr[32];
#pragma unroll
        for (int c = 0; c < 8; c++) {
            float4 t = *(const float4*)(Xp + i * 32 + c * 4);
            xr[c*4+0] = t.x; xr[c*4+1] = t.y; xr[c*4+2] = t.z; xr[c*4+3] = t.w;
        }

#pragma unroll 1
        for (int cblk = 0; cblk < 4; cblk++) {
            int c = cblk * 32 + jg * 4;
            u64 w01 = 0, w23 = 0, u01 = 0, u23 = 0;
#pragma unroll
            for (int kk = 0; kk < 32; kk++) {
                ulonglong2 k2v = *(const ulonglong2*)(kn   + kk * PW + c);
                ulonglong2 v2v = *(const ulonglong2*)(vbkt + kk * PW + c);
                float xbv = xr[kk] * nbeta_s[kk];
                u64 xb2, xr2;
                PK2(xb2, xbv, xbv); PK2(xr2, xr[kk], xr[kk]);
                FMA2(w01, xb2, k2v.x, w01); FMA2(w23, xb2, k2v.y, w23);
                FMA2(u01, xr2, v2v.x, u01); FMA2(u23, xr2, v2v.y, u23);
            }
            ulonglong2 ow; ow.x = w01; ow.y = w23;
            ulonglong2 ou; ou.x = u01; ou.y = u23;
            *(ulonglong2*)(g_w + base + i * 128 + c) = ow;
            *(ulonglong2*)(g_u + base + i * 128 + c) = ou;
        }
    }
}

// ---------------------------------------------------------------------------
// Kernel 2: sequential scan, 512 threads, K-split QUARTERS, 2-row main
// blocking; UPDATE re-blocked to 4 rows x 4 cols on 256 threads.
// ---------------------------------------------------------------------------
#define BUF_FLOATS (3 * 32 * PW + 2 * 32 * PS)   // 12672 + 2304 = 14976

extern __shared__ float sm2[];

__device__ __forceinline__ void k2_prefetch(int n, float* buf, int bh, int sl, int tid) {
    const size_t tb = ((size_t)bh * 128 + n) * 4096;
    float* w = buf;
    float* q = buf + 32 * PW;
    float* k = buf + 64 * PW;
    float* u = buf + 96 * PW;
    float* a = buf + 96 * PW + 32 * PS;
#pragma unroll
    for (int t = 0; t < 2; t++) {
        int idx = tid + t * 512;               // 0..1023
        int r = idx >> 5, c4 = (idx & 31) << 2;
        cpa16(w + r * PW + c4, g_w  + tb + r * 128 + c4);
        cpa16(q + r * PW + c4, g_qn + tb + r * 128 + c4);
        cpa16(k + r * PW + c4, g_kn + tb + r * 128 + c4);
    }
    if (tid < 256) {
        int r = tid >> 3, c4 = (tid & 7) << 2;
        cpa16(u + r * PS + c4, g_u + tb + r * 128 + sl * 32 + c4);
    } else {
        int t2 = tid - 256;
        int r = t2 >> 3, c4 = (t2 & 7) << 2;
        cpa16(a + r * PS + c4, g_attn + ((size_t)bh * 128 + n) * 1024 + r * 32 + c4);
    }
}

__global__ void __launch_bounds__(512, 1)
k2_kernel(float* __restrict__ out, int out_size) {
    float* S    = sm2;                        // 128*PS = 4608
    float* uish = S + 128 * PS;               // 32*PS
    float* pA   = uish + 32 * PS;             // 4 * 32*PS
    float* pO   = pA + 4 * 32 * PS;           // 4 * 32*PS
    float* bufs = pO + 4 * 32 * PS;           // 2*BUF_FLOATS

    const int tid = threadIdx.x;
    const int sl  = blockIdx.x;
    const int bh  = blockIdx.z * 16 + blockIdx.y;
    // main-loop mapping: quarter h, 16 row-pairs x 8 col groups
    const int h   = tid >> 7;                 // K-quarter 0..3
    const int t7  = tid & 127;
    const int r0  = t7 >> 3;                  // 0..15
    const int r1  = r0 + 16;
    const int j4  = (t7 & 7) << 2;
    const int kb  = h * 32;                   // K base for this quarter
    // combine/epilogue mapping (tid < 256)
    const int ci  = tid >> 3;                 // 0..31
    const int cj4 = (tid & 7) << 2;
    // update mapping (tid < 256): 4 contig rows x 4 cols
    const int ur0 = (tid >> 3) << 2;          // 0..124 (32 quads)
    const int uj4 = (tid & 7) << 2;           // 0..28

    for (int x = tid; x < 128 * PS; x += 512) S[x] = 0.f;

    k2_prefetch(0, bufs, bh, sl, tid);
    CP_COMMIT();

#pragma unroll 1
    for (int n = 0; n < 128; n++) {
        float* buf = bufs + (n & 1) * BUF_FLOATS;
        CP_WAIT0();
        __syncthreads();                                   // A
        if (n + 1 < 128) { k2_prefetch(n + 1, bufs + ((n + 1) & 1) * BUF_FLOATS, bh, sl, tid); CP_COMMIT(); }

        const float* w = buf;
        const float* q = buf + 32 * PW;
        const float* k = buf + 64 * PW;
        const float* u = buf + 96 * PW;
        const float* a = buf + 96 * PW + 32 * PS;

        // main: 2 rows x 4 cols per thread over this quarter's K=32
        u64 A0a = 0, A0b = 0, O0a = 0, O0b = 0;
        u64 A1a = 0, A1b = 0, O1a = 0, O1b = 0;
#pragma unroll 2
        for (int kk4 = 0; kk4 < 8; kk4++) {
            float4 w40 = *(const float4*)(w + r0 * PW + kb + kk4 * 4);
            float4 w41 = *(const float4*)(w + r1 * PW + kb + kk4 * 4);
            float4 q40 = *(const float4*)(q + r0 * PW + kb + kk4 * 4);
            float4 q41 = *(const float4*)(q + r1 * PW + kb + kk4 * 4);
#define MSTEP(m, w0c, w1c, q0c, q1c)                                            \
            {                                                                   \
                ulonglong2 s2 = *(const ulonglong2*)(S + (kb + kk4*4 + m) * PS + j4); \
                u64 w0p, w1p, q0p, q1p;                                         \
                PK2(w0p, w0c, w0c); PK2(w1p, w1c, w1c);                         \
                PK2(q0p, q0c, q0c); PK2(q1p, q1c, q1c);                         \
                FMA2(A0a, w0p, s2.x, A0a); FMA2(A0b, w0p, s2.y, A0b);           \
                FMA2(O0a, q0p, s2.x, O0a); FMA2(O0b, q0p, s2.y, O0b);           \
                FMA2(A1a, w1p, s2.x, A1a); FMA2(A1b, w1p, s2.y, A1b);           \
                FMA2(O1a, q1p, s2.x, O1a); FMA2(O1b, q1p, s2.y, O1b);           \
            }
            MSTEP(0, w40.x, w41.x, q40.x, q41.x)
            MSTEP(1, w40.y, w41.y, q40.y, q41.y)
            MSTEP(2, w40.z, w41.z, q40.z, q41.z)
            MSTEP(3, w40.w, w41.w, q40.w, q41.w)
#undef MSTEP
        }
        // publish partials (all threads, group h)
        {
            float* gA = pA + h * 32 * PS;
            float* gO = pO + h * 32 * PS;
            *(u64*)(gA + r0 * PS + j4)     = A0a;
            *(u64*)(gA + r0 * PS + j4 + 2) = A0b;
            *(u64*)(gA + r1 * PS + j4)     = A1a;
            *(u64*)(gA + r1 * PS + j4 + 2) = A1b;
            *(u64*)(gO + r0 * PS + j4)     = O0a;
            *(u64*)(gO + r0 * PS + j4 + 2) = O0b;
            *(u64*)(gO + r1 * PS + j4)     = O1a;
            *(u64*)(gO + r1 * PS + j4 + 2) = O1b;
        }
        __syncthreads();                                   // B
        u64 ao01 = 0, ao23 = 0;
        if (tid < 256) {
            ulonglong2 t = *(const ulonglong2*)(u + ci * PS + cj4);
            u64 aui01 = t.x, aui23 = t.y;
#pragma unroll
            for (int g = 0; g < 4; g++) {
                ADD2(aui01, aui01, *(const u64*)(pA + g * 32 * PS + ci * PS + cj4));
                ADD2(aui23, aui23, *(const u64*)(pA + g * 32 * PS + ci * PS + cj4 + 2));
                ADD2(ao01,  ao01,  *(const u64*)(pO + g * 32 * PS + ci * PS + cj4));
                ADD2(ao23,  ao23,  *(const u64*)(pO + g * 32 * PS + ci * PS + cj4 + 2));
            }
            *(u64*)(uish + ci * PS + cj4)     = aui01;
            *(u64*)(uish + ci * PS + cj4 + 2) = aui23;
        }
        __syncthreads();                                   // C
        if (tid < 256) {
            // o = ao + attn @ ui
#pragma unroll
            for (int c4 = 0; c4 < 8; c4++) {
                float4 a4 = *(const float4*)(a + ci * PS + c4 * 4);
#define ASTEP(m, ac)                                                            \
                {                                                               \
                    ulonglong2 uu = *(const ulonglong2*)(uish + (c4*4 + m) * PS + cj4); \
                    u64 a2; PK2(a2, ac, ac);                                    \
                    FMA2(ao01, a2, uu.x, ao01); FMA2(ao23, a2, uu.y, ao23);     \
                }
                ASTEP(0, a4.x) ASTEP(1, a4.y) ASTEP(2, a4.z) ASTEP(3, a4.w)
#undef ASTEP
            }
            ulonglong2 ov; ov.x = ao01; ov.y = ao23;
            *(ulonglong2*)(out + ((size_t)bh * 4096 + n * 32 + ci) * 128 + sl * 32 + cj4) = ov;

            // S += kn^T @ ui  (256 threads; 4 contig rows x 4 cols each)
            u64 s0a = *(const u64*)(S + (ur0 + 0) * PS + uj4);
            u64 s0b = *(const u64*)(S + (ur0 + 0) * PS + uj4 + 2);
            u64 s1a = *(const u64*)(S + (ur0 + 1) * PS + uj4);
            u64 s1b = *(const u64*)(S + (ur0 + 1) * PS + uj4 + 2);
            u64 s2a = *(const u64*)(S + (ur0 + 2) * PS + uj4);
            u64 s2b = *(const u64*)(S + (ur0 + 2) * PS + uj4 + 2);
            u64 s3a = *(const u64*)(S + (ur0 + 3) * PS + uj4);
            u64 s3b = *(const u64*)(S + (ur0 + 3) * PS + uj4 + 2);
#pragma unroll 4
            for (int c = 0; c < 32; c++) {
                float4 k4 = *(const float4*)(k + c * PW + ur0);
                ulonglong2 uu = *(const ulonglong2*)(uish + c * PS + uj4);
                u64 k0p, k1p, k2p, k3p;
                PK2(k0p, k4.x, k4.x); PK2(k1p, k4.y, k4.y);
                PK2(k2p, k4.z, k4.z); PK2(k3p, k4.w, k4.w);
                FMA2(s0a, k0p, uu.x, s0a); FMA2(s0b, k0p, uu.y, s0b);
                FMA2(s1a, k1p, uu.x, s1a); FMA2(s1b, k1p, uu.y, s1b);
                FMA2(s2a, k2p, uu.x, s2a); FMA2(s2b, k2p, uu.y, s2b);
                FMA2(s3a, k3p, uu.x, s3a); FMA2(s3b, k3p, uu.y, s3b);
            }
            *(u64*)(S + (ur0 + 0) * PS + uj4)     = s0a;
            *(u64*)(S + (ur0 + 0) * PS + uj4 + 2) = s0b;
            *(u64*)(S + (ur0 + 1) * PS + uj4)     = s1a;
            *(u64*)(S + (ur0 + 1) * PS + uj4 + 2) = s1b;
            *(u64*)(S + (ur0 + 2) * PS + uj4)     = s2a;
            *(u64*)(S + (ur0 + 2) * PS + uj4 + 2) = s2b;
            *(u64*)(S + (ur0 + 3) * PS + uj4)     = s3a;
            *(u64*)(S + (ur0 + 3) * PS + uj4 + 2) = s3b;
        }
    }
    __syncthreads();

    // final state S -> second output tensor (b,h,dk,dv)
    if (out_size >= OUT_ELEMS + S_ELEMS) {
        int ii = tid >> 3;                  // 0..63
        int jj4 = (tid & 7) << 2;
#pragma unroll
        for (int rb = 0; rb < 2; rb++) {
            int kd = ii + rb * 64;
            *(ulonglong2*)(out + OUT_ELEMS + ((size_t)bh * 128 + kd) * 128 + sl * 32 + jj4) =
                *(const ulonglong2*)(S + kd * PS + jj4);
        }
    }
}

// ---------------------------------------------------------------------------
extern "C" void kernel_launch(void* const* d_in, const int* in_sizes, int n_in,
                              void* d_out, int out_size) {
    const float* q    = (const float*)d_in[0];
    const float* k    = (const float*)d_in[1];
    const float* v    = (const float*)d_in[2];
    const float* beta = (const float*)d_in[3];
    float* out = (float*)d_out;

    const int k1_smem = (3 * 32 * PW + 4 * 1024 + 64) * 4;                       // 67,456 B
    const int k2_smem = (128 * PS + 9 * 32 * PS + 2 * BUF_FLOATS) * 4;           // 179,712 B

    cudaFuncSetAttribute(k1_kernel, cudaFuncAttributeMaxDynamicSharedMemorySize, k1_smem);
    cudaFuncSetAttribute(k2_kernel, cudaFuncAttributeMaxDynamicSharedMemorySize, k2_smem);

    k1_kernel<<<NTILES, 256, k1_smem>>>(q, k, v, beta);
    k2_kernel<<<dim3(4, 16, 2), 512, k2_smem>>>(out, out_size);
}

// round 16
// speedup vs baseline: 1.2352x; 1.0024x over previous
#include <cuda_runtime.h>
#include <cstdint>

// Problem constants: b=2, h=16, L=4096, d=128, chunk=32
#define NTILES   4096
#define OUT_ELEMS 16777216
#define S_ELEMS   524288
#define PW 132                   // padded stride for 128-wide rows
#define PS 36                    // padded stride for 32-wide rows

typedef unsigned long long u64;

// Scratch (static device globals). g_w holds NEGATED w.
__device__ float g_qn[16777216];
__device__ float g_kn[16777216];
__device__ float g_w [16777216];
__device__ float g_u [16777216];
__device__ float g_attn[4194304];

#define FMA2(d, a, b, c) asm("fma.rn.f32x2 %0, %1, %2, %3;" : "=l"(d) : "l"(a), "l"(b), "l"(c))
#define ADD2(d, a, b)    asm("add.rn.f32x2 %0, %1, %2;"     : "=l"(d) : "l"(a), "l"(b))
#define PK2(d, lo, hi)   asm("mov.b64 %0, {%1, %2};"        : "=l"(d) : "f"(lo), "f"(hi))
#define UPK2(lo, hi, s)  asm("mov.b64 {%0, %1}, %2;"        : "=f"(lo), "=f"(hi) : "l"(s))

__device__ __forceinline__ void cpa16(float* dst_smem, const float* src_gmem) {
    uint32_t d = (uint32_t)__cvta_generic_to_shared(dst_smem);
    asm volatile("cp.async.cg.shared.global [%0], [%1], 16;\n" :: "r"(d), "l"(src_gmem));
}
#define CP_COMMIT() asm volatile("cp.async.commit_group;\n" ::: "memory")
#define CP_WAIT0()  asm volatile("cp.async.wait_group 0;\n" ::: "memory")

// 32x32 matmul on shared (stride-32): out = (adds? adds:0) + a @ b   (f32x2)
__device__ __forceinline__ void mm32(float* __restrict__ out,
                                     const float* __restrict__ a,
                                     const float* __restrict__ b,
                                     const float* __restrict__ adds,
                                     int tid) {
    int i  = tid >> 3;
    int j4 = (tid & 7) << 2;
    float ar[32];
#pragma unroll
    for (int c = 0; c < 8; c++) {
        float4 t = *(const float4*)(a + i * 32 + c * 4);
        ar[c*4+0] = t.x; ar[c*4+1] = t.y; ar[c*4+2] = t.z; ar[c*4+3] = t.w;
    }
    u64 acc01 = 0, acc23 = 0;
    if (adds) {
        ulonglong2 ad = *(const ulonglong2*)(adds + i * 32 + j4);
        acc01 = ad.x; acc23 = ad.y;
    }
#pragma unroll
    for (int kk = 0; kk < 32; kk++) {
        ulonglong2 b2 = *(const ulonglong2*)(b + kk * 32 + j4);
        u64 a2; PK2(a2, ar[kk], ar[kk]);
        FMA2(acc01, a2, b2.x, acc01);
        FMA2(acc23, a2, b2.y, acc23);
    }
    ulonglong2 o; o.x = acc01; o.y = acc23;
    *(ulonglong2*)(out + i * 32 + j4) = o;
}

// ---------------------------------------------------------------------------
// Kernel 1: per chunk-tile (4096 CTAs). (unchanged)
// ---------------------------------------------------------------------------
extern __shared__ float sm1[];

__global__ void __launch_bounds__(256, 3)
k1_kernel(const float* __restrict__ q, const float* __restrict__ k,
          const float* __restrict__ v, const float* __restrict__ beta) {
    float* qn   = sm1;               // 32*PW
    float* kn   = qn + 32 * PW;      // 32*PW
    float* vbkt = kn + 32 * PW;      // 32*PW  (kt first, vb later)
    float* Am = vbkt + 32 * PW;      // 1024
    float* Bm = Am + 1024;
    float* Xm = Bm + 1024;
    float* Ym = Xm + 1024;
    float* beta_s  = Ym + 1024;      // 32
    float* nbeta_s = beta_s + 32;    // 32

    const int tid  = threadIdx.x;
    const int tile = blockIdx.x;
    const size_t base = (size_t)tile * 4096;
    const int brow = tile * 32;

    {
        int wp = tid >> 5, lane = tid & 31;
#pragma unroll
        for (int rr = 0; rr < 4; rr++) {
            int r = wp * 4 + rr;
            float4 a = *(const float4*)(q + base + r * 128 + lane * 4);
            float s = a.x*a.x + a.y*a.y + a.z*a.z + a.w*a.w;
#pragma unroll
            for (int off = 16; off; off >>= 1) s += __shfl_xor_sync(0xffffffffu, s, off);
            float sc = rsqrtf(s + 1e-6f);
            float4 o = make_float4(a.x*sc, a.y*sc, a.z*sc, a.w*sc);
            *(float4*)(qn + r * PW + lane * 4) = o;
            *(float4*)(g_qn + base + r * 128 + lane * 4) = o;

            float4 b = *(const float4*)(k + base + r * 128 + lane * 4);
            float sk = b.x*b.x + b.y*b.y + b.z*b.z + b.w*b.w;
#pragma unroll
            for (int off = 16; off; off >>= 1) sk += __shfl_xor_sync(0xffffffffu, sk, off);
            float sck = rsqrtf(sk + 1e-6f);
            float4 ok = make_float4(b.x*sck, b.y*sck, b.z*sck, b.w*sck);
            *(float4*)(kn + r * PW + lane * 4) = ok;
            *(float4*)(g_kn + base + r * 128 + lane * 4) = ok;
        }
        if (tid < 32) {
            float b = beta[brow + tid];
            beta_s[tid] = b;
            nbeta_s[tid] = -b;
        }
    }
    __syncthreads();

    // kt (128 x 32) into vbkt
    {
#pragma unroll
        for (int t = 0; t < 4; t++) {
            int idx = tid + t * 256;
            int r = idx & 31, g = idx >> 5;
            float4 f = *(const float4*)(kn + r * PW + g * 4);
            vbkt[(4*g+0) * 32 + r] = f.x;
            vbkt[(4*g+1) * 32 + r] = f.y;
            vbkt[(4*g+2) * 32 + r] = f.z;
            vbkt[(4*g+3) * 32 + r] = f.w;
        }
    }
    __syncthreads();

    // T0/attn
    {
        const float* kt = vbkt;
        const int h  = tid >> 7;
        const int t  = tid & 127;
        const int r0 = (t >> 3) * 2, r1 = r0 + 1;
        const int j4 = (t & 7) << 2;
        u64 aK0a=0,aK0b=0,aK1a=0,aK1b=0, aQ0a=0,aQ0b=0,aQ1a=0,aQ1b=0;
        const int c0 = h * 64;
#pragma unroll 4
        for (int c = c0; c < c0 + 64; c++) {
            ulonglong2 kt2 = *(const ulonglong2*)(kt + c * 32 + j4);
            float k0v = kn[r0*PW + c], k1v = kn[r1*PW + c];
            float q0v = qn[r0*PW + c], q1v = qn[r1*PW + c];
            u64 k02,k12,q02,q12;
            PK2(k02,k0v,k0v); PK2(k12,k1v,k1v); PK2(q02,q0v,q0v); PK2(q12,q1v,q1v);
            FMA2(aK0a,k02,kt2.x,aK0a); FMA2(aK0b,k02,kt2.y,aK0b);
            FMA2(aK1a,k12,kt2.x,aK1a); FMA2(aK1b,k12,kt2.y,aK1b);
            FMA2(aQ0a,q02,kt2.x,aQ0a); FMA2(aQ0b,q02,kt2.y,aQ0b);
            FMA2(aQ1a,q12,kt2.x,aQ1a); FMA2(aQ1b,q12,kt2.y,aQ1b);
        }
        if (h == 1) {
            *(u64*)(Bm + r0*32 + j4)   = aK0a; *(u64*)(Bm + r0*32 + j4+2) = aK0b;
            *(u64*)(Bm + r1*32 + j4)   = aK1a; *(u64*)(Bm + r1*32 + j4+2) = aK1b;
            *(u64*)(Ym + r0*32 + j4)   = aQ0a; *(u64*)(Ym + r0*32 + j4+2) = aQ0b;
            *(u64*)(Ym + r1*32 + j4)   = aQ1a; *(u64*)(Ym + r1*32 + j4+2) = aQ1b;
        }
        __syncthreads();
        if (h == 0) {
            ADD2(aK0a, aK0a, *(const u64*)(Bm + r0*32 + j4));
            ADD2(aK0b, aK0b, *(const u64*)(Bm + r0*32 + j4+2));
            ADD2(aK1a, aK1a, *(const u64*)(Bm + r1*32 + j4));
            ADD2(aK1b, aK1b, *(const u64*)(Bm + r1*32 + j4+2));
            ADD2(aQ0a, aQ0a, *(const u64*)(Ym + r0*32 + j4));
            ADD2(aQ0b, aQ0b, *(const u64*)(Ym + r0*32 + j4+2));
            ADD2(aQ1a, aQ1a, *(const u64*)(Ym + r1*32 + j4));
            ADD2(aQ1b, aQ1b, *(const u64*)(Ym + r1*32 + j4+2));
            float K0[4], K1[4], Q0[4], Q1[4];
            UPK2(K0[0],K0[1],aK0a); UPK2(K0[2],K0[3],aK0b);
            UPK2(K1[0],K1[1],aK1a); UPK2(K1[2],K1[3],aK1b);
            UPK2(Q0[0],Q0[1],aQ0a); UPK2(Q0[2],Q0[3],aQ0b);
            UPK2(Q1[0],Q1[1],aQ1a); UPK2(Q1[2],Q1[3],aQ1b);
#pragma unroll
            for (int rr = 0; rr < 2; rr++) {
                int row = r0 + rr;
                const float* K = rr ? K1 : K0;
                const float* Q = rr ? Q1 : Q0;
                float bb = beta_s[row];
                float att[4];
#pragma unroll
                for (int m = 0; m < 4; m++) {
                    int j = j4 + m;
                    float t0 = (row > j) ? (-bb * K[m]) : 0.f;
                    Am[row*32 + j] = t0;
                    Xm[row*32 + j] = t0 + ((row == j) ? 1.f : 0.f);
                    att[m] = (row >= j) ? Q[m] : 0.f;
                }
                *(float4*)(g_attn + (size_t)tile * 1024 + row * 32 + j4) =
                    make_float4(att[0], att[1], att[2], att[3]);
            }
        }
        __syncthreads();
    }

    // (I - T0)^{-1} via nilpotent squaring
    float *Ap = Am, *Bp = Bm, *Xp = Xm, *Yp = Ym;
#pragma unroll 1
    for (int s = 0; s < 4; s++) {
        mm32(Bp, Ap, Ap, nullptr, tid);
        __syncthreads();
        mm32(Yp, Xp, Bp, Xp, tid);
        __syncthreads();
        float* t;
        t = Ap; Ap = Bp; Bp = t;
        t = Xp; Xp = Yp; Yp = t;
    }

    // vb = v * beta
    for (int x = tid; x < 1024; x += 256) {
        int r = x >> 5, c4 = (x & 31) << 2;
        float4 vv = *(const float4*)(v + base + r * 128 + c4);
        float bb = beta_s[r];
        *(float4*)(vbkt + r * PW + c4) = make_float4(vv.x*bb, vv.y*bb, vv.z*bb, vv.w*bb);
    }
    __syncthreads();

    // g_w = -(Xp @ (kn * beta)), g_u = Xp @ vb
    {
        int i  = tid >> 3;
        int jg = tid & 7;
        float xr[32];
#pragma unroll
        for (int c = 0; c < 8; c++) {
            float4 t = *(const float4*)(Xp + i * 32 + c * 4);
            xr[c*4+0] = t.x; xr[c*4+1] = t.y; xr[c*4+2] = t.z; xr[c*4+3] = t.w;
        }

#pragma unroll 1
        for (int cblk = 0; cblk < 4; cblk++) {
            int c = cblk * 32 + jg * 4;
            u64 w01 = 0, w23 = 0, u01 = 0, u23 = 0;
#pragma unroll
            for (int kk = 0; kk < 32; kk++) {
                ulonglong2 k2v = *(const ulonglong2*)(kn   + kk * PW + c);
                ulonglong2 v2v = *(const ulonglong2*)(vbkt + kk * PW + c);
                float xbv = xr[kk] * nbeta_s[kk];
                u64 xb2, xr2;
                PK2(xb2, xbv, xbv); PK2(xr2, xr[kk], xr[kk]);
                FMA2(w01, xb2, k2v.x, w01); FMA2(w23, xb2, k2v.y, w23);
                FMA2(u01, xr2, v2v.x, u01); FMA2(u23, xr2, v2v.y, u23);
            }
            ulonglong2 ow; ow.x = w01; ow.y = w23;
            ulonglong2 ou; ou.x = u01; ou.y = u23;
            *(ulonglong2*)(g_w + base + i * 128 + c) = ow;
            *(ulonglong2*)(g_u + base + i * 128 + c) = ou;
        }
    }
}

// ---------------------------------------------------------------------------
// Kernel 2: sequential scan, 512 threads, K-split QUARTERS, 2-row main
// blocking; post-combine epilogue SPLIT: tid<256 attn+store, tid>=256 S-update.
// ---------------------------------------------------------------------------
#define BUF_FLOATS (3 * 32 * PW + 2 * 32 * PS)   // 12672 + 2304 = 14976

extern __shared__ float sm2[];

__device__ __forceinline__ void k2_prefetch(int n, float* buf, int bh, int sl, int tid) {
    const size_t tb = ((size_t)bh * 128 + n) * 4096;
    float* w = buf;
    float* q = buf + 32 * PW;
    float* k = buf + 64 * PW;
    float* u = buf + 96 * PW;
    float* a = buf + 96 * PW + 32 * PS;
#pragma unroll
    for (int t = 0; t < 2; t++) {
        int idx = tid + t * 512;               // 0..1023
        int r = idx >> 5, c4 = (idx & 31) << 2;
        cpa16(w + r * PW + c4, g_w  + tb + r * 128 + c4);
        cpa16(q + r * PW + c4, g_qn + tb + r * 128 + c4);
        cpa16(k + r * PW + c4, g_kn + tb + r * 128 + c4);
    }
    if (tid < 256) {
        int r = tid >> 3, c4 = (tid & 7) << 2;
        cpa16(u + r * PS + c4, g_u + tb + r * 128 + sl * 32 + c4);
    } else {
        int t2 = tid - 256;
        int r = t2 >> 3, c4 = (t2 & 7) << 2;
        cpa16(a + r * PS + c4, g_attn + ((size_t)bh * 128 + n) * 1024 + r * 32 + c4);
    }
}

__global__ void __launch_bounds__(512, 1)
k2_kernel(float* __restrict__ out, int out_size) {
    float* S    = sm2;                        // 128*PS = 4608
    float* uish = S + 128 * PS;               // 32*PS
    float* pA   = uish + 32 * PS;             // 4 * 32*PS
    float* pO   = pA + 4 * 32 * PS;           // 4 * 32*PS
    float* bufs = pO + 4 * 32 * PS;           // 2*BUF_FLOATS

    const int tid = threadIdx.x;
    const int sl  = blockIdx.x;
    const int bh  = blockIdx.z * 16 + blockIdx.y;
    // main-loop mapping: quarter h, 16 row-pairs x 8 col groups
    const int h   = tid >> 7;                 // K-quarter 0..3
    const int t7  = tid & 127;
    const int r0  = t7 >> 3;                  // 0..15
    const int r1  = r0 + 16;
    const int j4  = (t7 & 7) << 2;
    const int kb  = h * 32;                   // K base for this quarter
    // combine/attn mapping (tid < 256)
    const int ci  = tid >> 3;                 // 0..31
    const int cj4 = (tid & 7) << 2;
    // update mapping (tid >= 256): 4 contig rows x 4 cols
    const int t2u = tid & 255;
    const int ur0 = (t2u >> 3) << 2;          // 0..124 (32 quads)
    const int uj4 = (t2u & 7) << 2;           // 0..28

    for (int x = tid; x < 128 * PS; x += 512) S[x] = 0.f;

    k2_prefetch(0, bufs, bh, sl, tid);
    CP_COMMIT();

#pragma unroll 1
    for (int n = 0; n < 128; n++) {
        float* buf = bufs + (n & 1) * BUF_FLOATS;
        CP_WAIT0();
        __syncthreads();                                   // A
        if (n + 1 < 128) { k2_prefetch(n + 1, bufs + ((n + 1) & 1) * BUF_FLOATS, bh, sl, tid); CP_COMMIT(); }

        const float* w = buf;
        const float* q = buf + 32 * PW;
        const float* k = buf + 64 * PW;
        const float* u = buf + 96 * PW;
        const float* a = buf + 96 * PW + 32 * PS;

        // main: 2 rows x 4 cols per thread over this quarter's K=32
        u64 A0a = 0, A0b = 0, O0a = 0, O0b = 0;
        u64 A1a = 0, A1b = 0, O1a = 0, O1b = 0;
#pragma unroll 2
        for (int kk4 = 0; kk4 < 8; kk4++) {
            float4 w40 = *(const float4*)(w + r0 * PW + kb + kk4 * 4);
            float4 w41 = *(const float4*)(w + r1 * PW + kb + kk4 * 4);
            float4 q40 = *(const float4*)(q + r0 * PW + kb + kk4 * 4);
            float4 q41 = *(const float4*)(q + r1 * PW + kb + kk4 * 4);
#define MSTEP(m, w0c, w1c, q0c, q1c)                                            \
            {                                                                   \
                ulonglong2 s2 = *(const ulonglong2*)(S + (kb + kk4*4 + m) * PS + j4); \
                u64 w0p, w1p, q0p, q1p;                                         \
                PK2(w0p, w0c, w0c); PK2(w1p, w1c, w1c);                         \
                PK2(q0p, q0c, q0c); PK2(q1p, q1c, q1c);                         \
                FMA2(A0a, w0p, s2.x, A0a); FMA2(A0b, w0p, s2.y, A0b);           \
                FMA2(O0a, q0p, s2.x, O0a); FMA2(O0b, q0p, s2.y, O0b);           \
                FMA2(A1a, w1p, s2.x, A1a); FMA2(A1b, w1p, s2.y, A1b);           \
                FMA2(O1a, q1p, s2.x, O1a); FMA2(O1b, q1p, s2.y, O1b);           \
            }
            MSTEP(0, w40.x, w41.x, q40.x, q41.x)
            MSTEP(1, w40.y, w41.y, q40.y, q41.y)
            MSTEP(2, w40.z, w41.z, q40.z, q41.z)
            MSTEP(3, w40.w, w41.w, q40.w, q41.w)
#undef MSTEP
        }
        // publish partials (all threads, group h)
        {
            float* gA = pA + h * 32 * PS;
            float* gO = pO + h * 32 * PS;
            *(u64*)(gA + r0 * PS + j4)     = A0a;
            *(u64*)(gA + r0 * PS + j4 + 2) = A0b;
            *(u64*)(gA + r1 * PS + j4)     = A1a;
            *(u64*)(gA + r1 * PS + j4 + 2) = A1b;
            *(u64*)(gO + r0 * PS + j4)     = O0a;
            *(u64*)(gO + r0 * PS + j4 + 2) = O0b;
            *(u64*)(gO + r1 * PS + j4)     = O1a;
            *(u64*)(gO + r1 * PS + j4 + 2) = O1b;
        }
        __syncthreads();                                   // B
        u64 ao01 = 0, ao23 = 0;
        if (tid < 256) {
            ulonglong2 t = *(const ulonglong2*)(u + ci * PS + cj4);
            u64 aui01 = t.x, aui23 = t.y;
#pragma unroll
            for (int g = 0; g < 4; g++) {
                ADD2(aui01, aui01, *(const u64*)(pA + g * 32 * PS + ci * PS + cj4));
                ADD2(aui23, aui23, *(const u64*)(pA + g * 32 * PS + ci * PS + cj4 + 2));
                ADD2(ao01,  ao01,  *(const u64*)(pO + g * 32 * PS + ci * PS + cj4));
                ADD2(ao23,  ao23,  *(const u64*)(pO + g * 32 * PS + ci * PS + cj4 + 2));
            }
            *(u64*)(uish + ci * PS + cj4)     = aui01;
            *(u64*)(uish + ci * PS + cj4 + 2) = aui23;
        }
        __syncthreads();                                   // C
        if (tid < 256) {
            // o = ao + attn @ ui ; store
#pragma unroll
            for (int c4 = 0; c4 < 8; c4++) {
                float4 a4 = *(const float4*)(a + ci * PS + c4 * 4);
#define ASTEP(m, ac)                                                            \
                {                                                               \
                    ulonglong2 uu = *(const ulonglong2*)(uish + (c4*4 + m) * PS + cj4); \
                    u64 a2; PK2(a2, ac, ac);                                    \
                    FMA2(ao01, a2, uu.x, ao01); FMA2(ao23, a2, uu.y, ao23);     \
                }
                ASTEP(0, a4.x) ASTEP(1, a4.y) ASTEP(2, a4.z) ASTEP(3, a4.w)
#undef ASTEP
            }
            ulonglong2 ov; ov.x = ao01; ov.y = ao23;
            *(ulonglong2*)(out + ((size_t)bh * 4096 + n * 32 + ci) * 128 + sl * 32 + cj4) = ov;
        } else {
            // S += kn^T @ ui  (threads 256..511; 4 contig rows x 4 cols each)
            u64 s0a = *(const u64*)(S + (ur0 + 0) * PS + uj4);
            u64 s0b = *(const u64*)(S + (ur0 + 0) * PS + uj4 + 2);
            u64 s1a = *(const u64*)(S + (ur0 + 1) * PS + uj4);
            u64 s1b = *(const u64*)(S + (ur0 + 1) * PS + uj4 + 2);
            u64 s2a = *(const u64*)(S + (ur0 + 2) * PS + uj4);
            u64 s2b = *(const u64*)(S + (ur0 + 2) * PS + uj4 + 2);
            u64 s3a = *(const u64*)(S + (ur0 + 3) * PS + uj4);
            u64 s3b = *(const u64*)(S + (ur0 + 3) * PS + uj4 + 2);
#pragma unroll 4
            for (int c = 0; c < 32; c++) {
                float4 k4 = *(const float4*)(k + c * PW + ur0);
                ulonglong2 uu = *(const ulonglong2*)(uish + c * PS + uj4);
                u64 k0p, k1p, k2p, k3p;
                PK2(k0p, k4.x, k4.x); PK2(k1p, k4.y, k4.y);
                PK2(k2p, k4.z, k4.z); PK2(k3p, k4.w, k4.w);
                FMA2(s0a, k0p, uu.x, s0a); FMA2(s0b, k0p, uu.y, s0b);
                FMA2(s1a, k1p, uu.x, s1a); FMA2(s1b, k1p, uu.y, s1b);
                FMA2(s2a, k2p, uu.x, s2a); FMA2(s2b, k2p, uu.y, s2b);
                FMA2(s3a, k3p, uu.x, s3a); FMA2(s3b, k3p, uu.y, s3b);
            }
            *(u64*)(S + (ur0 + 0) * PS + uj4)     = s0a;
            *(u64*)(S + (ur0 + 0) * PS + uj4 + 2) = s0b;
            *(u64*)(S + (ur0 + 1) * PS + uj4)     = s1a;
            *(u64*)(S + (ur0 + 1) * PS + uj4 + 2) = s1b;
            *(u64*)(S + (ur0 + 2) * PS + uj4)     = s2a;
            *(u64*)(S + (ur0 + 2) * PS + uj4 + 2) = s2b;
            *(u64*)(S + (ur0 + 3) * PS + uj4)     = s3a;
            *(u64*)(S + (ur0 + 3) * PS + uj4 + 2) = s3b;
        }
    }
    __syncthreads();

    // final state S -> second output tensor (b,h,dk,dv)
    if (out_size >= OUT_ELEMS + S_ELEMS) {
        int ii = tid >> 3;                  // 0..63
        int jj4 = (tid & 7) << 2;
#pragma unroll
        for (int rb = 0; rb < 2; rb++) {
            int kd = ii + rb * 64;
            *(ulonglong2*)(out + OUT_ELEMS + ((size_t)bh * 128 + kd) * 128 + sl * 32 + jj4) =
                *(const ulonglong2*)(S + kd * PS + jj4);
        }
    }
}

// ---------------------------------------------------------------------------
extern "C" void kernel_launch(void* const* d_in, const int* in_sizes, int n_in,
                              void* d_out, int out_size) {
    const float* q    = (const float*)d_in[0];
    const float* k    = (const float*)d_in[1];
    const float* v    = (const float*)d_in[2];
    const float* beta = (const float*)d_in[3];
    float* out = (float*)d_out;

    const int k1_smem = (3 * 32 * PW + 4 * 1024 + 64) * 4;                       // 67,456 B
    const int k2_smem = (128 * PS + 9 * 32 * PS + 2 * BUF_FLOATS) * 4;           // 179,712 B

    cudaFuncSetAttribute(k1_kernel, cudaFuncAttributeMaxDynamicSharedMemorySize, k1_smem);
    cudaFuncSetAttribute(k2_kernel, cudaFuncAttributeMaxDynamicSharedMemorySize, k2_smem);

    k1_kernel<<<NTILES, 256, k1_smem>>>(q, k, v, beta);
    k2_kernel<<<dim3(4, 16, 2), 512, k2_smem>>>(out, out_size);
}

// round 17
// speedup vs baseline: 1.2723x; 1.0301x over previous
#include <cuda_runtime.h>
#include <cstdint>

// Problem constants: b=2, h=16, L=4096, d=128, chunk=32
#define NTILES   4096
#define OUT_ELEMS 16777216
#define S_ELEMS   524288
#define PW 132                   // padded stride for 128-wide rows
#define PS 36                    // padded stride for 32-wide rows

typedef unsigned long long u64;

// Scratch (static device globals). g_w holds NEGATED w.
__device__ float g_qn[16777216];
__device__ float g_kn[16777216];
__device__ float g_w [16777216];
__device__ float g_u [16777216];
__device__ float g_attn[4194304];

#define FMA2(d, a, b, c) asm("fma.rn.f32x2 %0, %1, %2, %3;" : "=l"(d) : "l"(a), "l"(b), "l"(c))
#define ADD2(d, a, b)    asm("add.rn.f32x2 %0, %1, %2;"     : "=l"(d) : "l"(a), "l"(b))
#define PK2(d, lo, hi)   asm("mov.b64 %0, {%1, %2};"        : "=l"(d) : "f"(lo), "f"(hi))
#define UPK2(lo, hi, s)  asm("mov.b64 {%0, %1}, %2;"        : "=f"(lo), "=f"(hi) : "l"(s))

__device__ __forceinline__ void cpa16(float* dst_smem, const float* src_gmem) {
    uint32_t d = (uint32_t)__cvta_generic_to_shared(dst_smem);
    asm volatile("cp.async.cg.shared.global [%0], [%1], 16;\n" :: "r"(d), "l"(src_gmem));
}
#define CP_COMMIT() asm volatile("cp.async.commit_group;\n" ::: "memory")
#define CP_WAIT0()  asm volatile("cp.async.wait_group 0;\n" ::: "memory")

// 32x32 matmul on shared (stride-32): out = (adds? adds:0) + a @ b   (f32x2)
__device__ __forceinline__ void mm32(float* __restrict__ out,
                                     const float* __restrict__ a,
                                     const float* __restrict__ b,
                                     const float* __restrict__ adds,
                                     int tid) {
    int i  = tid >> 3;
    int j4 = (tid & 7) << 2;
    float ar[32];
#pragma unroll
    for (int c = 0; c < 8; c++) {
        float4 t = *(const float4*)(a + i * 32 + c * 4);
        ar[c*4+0] = t.x; ar[c*4+1] = t.y; ar[c*4+2] = t.z; ar[c*4+3] = t.w;
    }
    u64 acc01 = 0, acc23 = 0;
    if (adds) {
        ulonglong2 ad = *(const ulonglong2*)(adds + i * 32 + j4);
        acc01 = ad.x; acc23 = ad.y;
    }
#pragma unroll
    for (int kk = 0; kk < 32; kk++) {
        ulonglong2 b2 = *(const ulonglong2*)(b + kk * 32 + j4);
        u64 a2; PK2(a2, ar[kk], ar[kk]);
        FMA2(acc01, a2, b2.x, acc01);
        FMA2(acc23, a2, b2.y, acc23);
    }
    ulonglong2 o; o.x = acc01; o.y = acc23;
    *(ulonglong2*)(out + i * 32 + j4) = o;
}

// ---------------------------------------------------------------------------
// Kernel 1: per chunk-tile (4096 CTAs). (unchanged)
// ---------------------------------------------------------------------------
extern __shared__ float sm1[];

__global__ void __launch_bounds__(256, 3)
k1_kernel(const float* __restrict__ q, const float* __restrict__ k,
          const float* __restrict__ v, const float* __restrict__ beta) {
    float* qn   = sm1;               // 32*PW
    float* kn   = qn + 32 * PW;      // 32*PW
    float* vbkt = kn + 32 * PW;      // 32*PW  (kt first, vb later)
    float* Am = vbkt + 32 * PW;      // 1024
    float* Bm = Am + 1024;
    float* Xm = Bm + 1024;
    float* Ym = Xm + 1024;
    float* beta_s  = Ym + 1024;      // 32
    float* nbeta_s = beta_s + 32;    // 32

    const int tid  = threadIdx.x;
    const int tile = blockIdx.x;
    const size_t base = (size_t)tile * 4096;
    const int brow = tile * 32;

    {
        int wp = tid >> 5, lane = tid & 31;
#pragma unroll
        for (int rr = 0; rr < 4; rr++) {
            int r = wp * 4 + rr;
            float4 a = *(const float4*)(q + base + r * 128 + lane * 4);
            float s = a.x*a.x + a.y*a.y + a.z*a.z + a.w*a.w;
#pragma unroll
            for (int off = 16; off; off >>= 1) s += __shfl_xor_sync(0xffffffffu, s, off);
            float sc = rsqrtf(s + 1e-6f);
            float4 o = make_float4(a.x*sc, a.y*sc, a.z*sc, a.w*sc);
            *(float4*)(qn + r * PW + lane * 4) = o;
            *(float4*)(g_qn + base + r * 128 + lane * 4) = o;

            float4 b = *(const float4*)(k + base + r * 128 + lane * 4);
            float sk = b.x*b.x + b.y*b.y + b.z*b.z + b.w*b.w;
#pragma unroll
            for (int off = 16; off; off >>= 1) sk += __shfl_xor_sync(0xffffffffu, sk, off);
            float sck = rsqrtf(sk + 1e-6f);
            float4 ok = make_float4(b.x*sck, b.y*sck, b.z*sck, b.w*sck);
            *(float4*)(kn + r * PW + lane * 4) = ok;
            *(float4*)(g_kn + base + r * 128 + lane * 4) = ok;
        }
        if (tid < 32) {
            float b = beta[brow + tid];
            beta_s[tid] = b;
            nbeta_s[tid] = -b;
        }
    }
    __syncthreads();

    // kt (128 x 32) into vbkt
    {
#pragma unroll
        for (int t = 0; t < 4; t++) {
            int idx = tid + t * 256;
            int r = idx & 31, g = idx >> 5;
            float4 f = *(const float4*)(kn + r * PW + g * 4);
            vbkt[(4*g+0) * 32 + r] = f.x;
            vbkt[(4*g+1) * 32 + r] = f.y;
            vbkt[(4*g+2) * 32 + r] = f.z;
            vbkt[(4*g+3) * 32 + r] = f.w;
        }
    }
    __syncthreads();

    // T0/attn
    {
        const float* kt = vbkt;
        const int h  = tid >> 7;
        const int t  = tid & 127;
        const int r0 = (t >> 3) * 2, r1 = r0 + 1;
        const int j4 = (t & 7) << 2;
        u64 aK0a=0,aK0b=0,aK1a=0,aK1b=0, aQ0a=0,aQ0b=0,aQ1a=0,aQ1b=0;
        const int c0 = h * 64;
#pragma unroll 4
        for (int c = c0; c < c0 + 64; c++) {
            ulonglong2 kt2 = *(const ulonglong2*)(kt + c * 32 + j4);
            float k0v = kn[r0*PW + c], k1v = kn[r1*PW + c];
            float q0v = qn[r0*PW + c], q1v = qn[r1*PW + c];
            u64 k02,k12,q02,q12;
            PK2(k02,k0v,k0v); PK2(k12,k1v,k1v); PK2(q02,q0v,q0v); PK2(q12,q1v,q1v);
            FMA2(aK0a,k02,kt2.x,aK0a); FMA2(aK0b,k02,kt2.y,aK0b);
            FMA2(aK1a,k12,kt2.x,aK1a); FMA2(aK1b,k12,kt2.y,aK1b);
            FMA2(aQ0a,q02,kt2.x,aQ0a); FMA2(aQ0b,q02,kt2.y,aQ0b);
            FMA2(aQ1a,q12,kt2.x,aQ1a); FMA2(aQ1b,q12,kt2.y,aQ1b);
        }
        if (h == 1) {
            *(u64*)(Bm + r0*32 + j4)   = aK0a; *(u64*)(Bm + r0*32 + j4+2) = aK0b;
            *(u64*)(Bm + r1*32 + j4)   = aK1a; *(u64*)(Bm + r1*32 + j4+2) = aK1b;
            *(u64*)(Ym + r0*32 + j4)   = aQ0a; *(u64*)(Ym + r0*32 + j4+2) = aQ0b;
            *(u64*)(Ym + r1*32 + j4)   = aQ1a; *(u64*)(Ym + r1*32 + j4+2) = aQ1b;
        }
        __syncthreads();
        if (h == 0) {
            ADD2(aK0a, aK0a, *(const u64*)(Bm + r0*32 + j4));
            ADD2(aK0b, aK0b, *(const u64*)(Bm + r0*32 + j4+2));
            ADD2(aK1a, aK1a, *(const u64*)(Bm + r1*32 + j4));
            ADD2(aK1b, aK1b, *(const u64*)(Bm + r1*32 + j4+2));
            ADD2(aQ0a, aQ0a, *(const u64*)(Ym + r0*32 + j4));
            ADD2(aQ0b, aQ0b, *(const u64*)(Ym + r0*32 + j4+2));
            ADD2(aQ1a, aQ1a, *(const u64*)(Ym + r1*32 + j4));
            ADD2(aQ1b, aQ1b, *(const u64*)(Ym + r1*32 + j4+2));
            float K0[4], K1[4], Q0[4], Q1[4];
            UPK2(K0[0],K0[1],aK0a); UPK2(K0[2],K0[3],aK0b);
            UPK2(K1[0],K1[1],aK1a); UPK2(K1[2],K1[3],aK1b);
            UPK2(Q0[0],Q0[1],aQ0a); UPK2(Q0[2],Q0[3],aQ0b);
            UPK2(Q1[0],Q1[1],aQ1a); UPK2(Q1[2],Q1[3],aQ1b);
#pragma unroll
            for (int rr = 0; rr < 2; rr++) {
                int row = r0 + rr;
                const float* K = rr ? K1 : K0;
                const float* Q = rr ? Q1 : Q0;
                float bb = beta_s[row];
                float att[4];
#pragma unroll
                for (int m = 0; m < 4; m++) {
                    int j = j4 + m;
                    float t0 = (row > j) ? (-bb * K[m]) : 0.f;
                    Am[row*32 + j] = t0;
                    Xm[row*32 + j] = t0 + ((row == j) ? 1.f : 0.f);
                    att[m] = (row >= j) ? Q[m] : 0.f;
                }
                *(float4*)(g_attn + (size_t)tile * 1024 + row * 32 + j4) =
                    make_float4(att[0], att[1], att[2], att[3]);
            }
        }
        __syncthreads();
    }

    // (I - T0)^{-1} via nilpotent squaring
    float *Ap = Am, *Bp = Bm, *Xp = Xm, *Yp = Ym;
#pragma unroll 1
    for (int s = 0; s < 4; s++) {
        mm32(Bp, Ap, Ap, nullptr, tid);
        __syncthreads();
        mm32(Yp, Xp, Bp, Xp, tid);
        __syncthreads();
        float* t;
        t = Ap; Ap = Bp; Bp = t;
        t = Xp; Xp = Yp; Yp = t;
    }

    // vb = v * beta
    for (int x = tid; x < 1024; x += 256) {
        int r = x >> 5, c4 = (x & 31) << 2;
        float4 vv = *(const float4*)(v + base + r * 128 + c4);
        float bb = beta_s[r];
        *(float4*)(vbkt + r * PW + c4) = make_float4(vv.x*bb, vv.y*bb, vv.z*bb, vv.w*bb);
    }
    __syncthreads();

    // g_w = -(Xp @ (kn * beta)), g_u = Xp @ vb
    {
        int i  = tid >> 3;
        int jg = tid & 7;
        float xr[32];
#pragma unroll
        for (int c = 0; c < 8; c++) {
            float4 t = *(const float4*)(Xp + i * 32 + c * 4);
            xr[c*4+0] = t.x; xr[c*4+1] = t.y; xr[c*4+2] = t.z; xr[c*4+3] = t.w;
        }

#pragma unroll 1
        for (int cblk = 0; cblk < 4; cblk++) {
            int c = cblk * 32 + jg * 4;
            u64 w01 = 0, w23 = 0, u01 = 0, u23 = 0;
#pragma unroll
            for (int kk = 0; kk < 32; kk++) {
                ulonglong2 k2v = *(const ulonglong2*)(kn   + kk * PW + c);
                ulonglong2 v2v = *(const ulonglong2*)(vbkt + kk * PW + c);
                float xbv = xr[kk] * nbeta_s[kk];
                u64 xb2, xr2;
                PK2(xb2, xbv, xbv); PK2(xr2, xr[kk], xr[kk]);
                FMA2(w01, xb2, k2v.x, w01); FMA2(w23, xb2, k2v.y, w23);
                FMA2(u01, xr2, v2v.x, u01); FMA2(u23, xr2, v2v.y, u23);
            }
            ulonglong2 ow; ow.x = w01; ow.y = w23;
            ulonglong2 ou; ou.x = u01; ou.y = u23;
            *(ulonglong2*)(g_w + base + i * 128 + c) = ow;
            *(ulonglong2*)(g_u + base + i * 128 + c) = ou;
        }
    }
}

// ---------------------------------------------------------------------------
// Kernel 2: sequential scan, 512 threads. Main loop: 256 threads, K-split-4,
// 4-ROW blocking (one S load feeds 4 rows x {A,O}). Epilogue split:
// tid<256 attn+store, tid>=256 S-update (4x4 blocking).
// ---------------------------------------------------------------------------
#define BUF_FLOATS (3 * 32 * PW + 2 * 32 * PS)   // 12672 + 2304 = 14976

extern __shared__ float sm2[];

__device__ __forceinline__ void k2_prefetch(int n, float* buf, int bh, int sl, int tid) {
    const size_t tb = ((size_t)bh * 128 + n) * 4096;
    float* w = buf;
    float* q = buf + 32 * PW;
    float* k = buf + 64 * PW;
    float* u = buf + 96 * PW;
    float* a = buf + 96 * PW + 32 * PS;
#pragma unroll
    for (int t = 0; t < 2; t++) {
        int idx = tid + t * 512;               // 0..1023
        int r = idx >> 5, c4 = (idx & 31) << 2;
        cpa16(w + r * PW + c4, g_w  + tb + r * 128 + c4);
        cpa16(q + r * PW + c4, g_qn + tb + r * 128 + c4);
        cpa16(k + r * PW + c4, g_kn + tb + r * 128 + c4);
    }
    if (tid < 256) {
        int r = tid >> 3, c4 = (tid & 7) << 2;
        cpa16(u + r * PS + c4, g_u + tb + r * 128 + sl * 32 + c4);
    } else {
        int t2 = tid - 256;
        int r = t2 >> 3, c4 = (t2 & 7) << 2;
        cpa16(a + r * PS + c4, g_attn + ((size_t)bh * 128 + n) * 1024 + r * 32 + c4);
    }
}

__global__ void __launch_bounds__(512, 1)
k2_kernel(float* __restrict__ out, int out_size) {
    float* S    = sm2;                        // 128*PS = 4608
    float* uish = S + 128 * PS;               // 32*PS
    float* pA   = uish + 32 * PS;             // 4 * 32*PS
    float* pO   = pA + 4 * 32 * PS;           // 4 * 32*PS
    float* bufs = pO + 4 * 32 * PS;           // 2*BUF_FLOATS

    const int tid = threadIdx.x;
    const int sl  = blockIdx.x;
    const int bh  = blockIdx.z * 16 + blockIdx.y;
    // main-loop mapping (tid < 256): K-quarter h, 8 row-quads x 8 col groups
    const int h   = tid >> 6;                 // 0..3
    const int t6  = tid & 63;
    const int rq  = (t6 >> 3) << 2;           // row base 0,4,..,28
    const int j4  = (t6 & 7) << 2;
    const int kb  = h * 32;                   // K base for this quarter
    // combine/attn mapping (tid < 256)
    const int ci  = tid >> 3;                 // 0..31
    const int cj4 = (tid & 7) << 2;
    // update mapping (tid >= 256): 4 contig rows x 4 cols
    const int t2u = tid & 255;
    const int ur0 = (t2u >> 3) << 2;          // 0..124 (32 quads)
    const int uj4 = (t2u & 7) << 2;           // 0..28

    for (int x = tid; x < 128 * PS; x += 512) S[x] = 0.f;

    k2_prefetch(0, bufs, bh, sl, tid);
    CP_COMMIT();

#pragma unroll 1
    for (int n = 0; n < 128; n++) {
        float* buf = bufs + (n & 1) * BUF_FLOATS;
        CP_WAIT0();
        __syncthreads();                                   // A
        if (n + 1 < 128) { k2_prefetch(n + 1, bufs + ((n + 1) & 1) * BUF_FLOATS, bh, sl, tid); CP_COMMIT(); }

        const float* w = buf;
        const float* q = buf + 32 * PW;
        const float* k = buf + 64 * PW;
        const float* u = buf + 96 * PW;
        const float* a = buf + 96 * PW + 32 * PS;

        // main (tid<256): 4 rows x 4 cols per thread over this quarter's K=32
        if (tid < 256) {
            u64 A0a=0,A0b=0,A1a=0,A1b=0,A2a=0,A2b=0,A3a=0,A3b=0;
            u64 O0a=0,O0b=0,O1a=0,O1b=0,O2a=0,O2b=0,O3a=0,O3b=0;
#pragma unroll 2
            for (int kk4 = 0; kk4 < 8; kk4++) {
                float4 w40 = *(const float4*)(w + (rq + 0) * PW + kb + kk4 * 4);
                float4 w41 = *(const float4*)(w + (rq + 1) * PW + kb + kk4 * 4);
                float4 w42 = *(const float4*)(w + (rq + 2) * PW + kb + kk4 * 4);
                float4 w43 = *(const float4*)(w + (rq + 3) * PW + kb + kk4 * 4);
                float4 q40 = *(const float4*)(q + (rq + 0) * PW + kb + kk4 * 4);
                float4 q41 = *(const float4*)(q + (rq + 1) * PW + kb + kk4 * 4);
                float4 q42 = *(const float4*)(q + (rq + 2) * PW + kb + kk4 * 4);
                float4 q43 = *(const float4*)(q + (rq + 3) * PW + kb + kk4 * 4);
#define MSTEP(m, w0c, w1c, w2c, w3c, q0c, q1c, q2c, q3c)                        \
                {                                                               \
                    ulonglong2 s2 = *(const ulonglong2*)(S + (kb + kk4*4 + m) * PS + j4); \
                    u64 w0p,w1p,w2p,w3p,q0p,q1p,q2p,q3p;                        \
                    PK2(w0p,w0c,w0c); PK2(w1p,w1c,w1c);                         \
                    PK2(w2p,w2c,w2c); PK2(w3p,w3c,w3c);                         \
                    PK2(q0p,q0c,q0c); PK2(q1p,q1c,q1c);                         \
                    PK2(q2p,q2c,q2c); PK2(q3p,q3c,q3c);                         \
                    FMA2(A0a,w0p,s2.x,A0a); FMA2(A0b,w0p,s2.y,A0b);             \
                    FMA2(O0a,q0p,s2.x,O0a); FMA2(O0b,q0p,s2.y,O0b);             \
                    FMA2(A1a,w1p,s2.x,A1a); FMA2(A1b,w1p,s2.y,A1b);             \
                    FMA2(O1a,q1p,s2.x,O1a); FMA2(O1b,q1p,s2.y,O1b);             \
                    FMA2(A2a,w2p,s2.x,A2a); FMA2(A2b,w2p,s2.y,A2b);             \
                    FMA2(O2a,q2p,s2.x,O2a); FMA2(O2b,q2p,s2.y,O2b);             \
                    FMA2(A3a,w3p,s2.x,A3a); FMA2(A3b,w3p,s2.y,A3b);             \
                    FMA2(O3a,q3p,s2.x,O3a); FMA2(O3b,q3p,s2.y,O3b);             \
                }
                MSTEP(0, w40.x,w41.x,w42.x,w43.x, q40.x,q41.x,q42.x,q43.x)
                MSTEP(1, w40.y,w41.y,w42.y,w43.y, q40.y,q41.y,q42.y,q43.y)
                MSTEP(2, w40.z,w41.z,w42.z,w43.z, q40.z,q41.z,q42.z,q43.z)
                MSTEP(3, w40.w,w41.w,w42.w,w43.w, q40.w,q41.w,q42.w,q43.w)
#undef MSTEP
            }
            // publish partials (group h)
            float* gA = pA + h * 32 * PS;
            float* gO = pO + h * 32 * PS;
            *(u64*)(gA + (rq+0) * PS + j4)     = A0a;
            *(u64*)(gA + (rq+0) * PS + j4 + 2) = A0b;
            *(u64*)(gA + (rq+1) * PS + j4)     = A1a;
            *(u64*)(gA + (rq+1) * PS + j4 + 2) = A1b;
            *(u64*)(gA + (rq+2) * PS + j4)     = A2a;
            *(u64*)(gA + (rq+2) * PS + j4 + 2) = A2b;
            *(u64*)(gA + (rq+3) * PS + j4)     = A3a;
            *(u64*)(gA + (rq+3) * PS + j4 + 2) = A3b;
            *(u64*)(gO + (rq+0) * PS + j4)     = O0a;
            *(u64*)(gO + (rq+0) * PS + j4 + 2) = O0b;
            *(u64*)(gO + (rq+1) * PS + j4)     = O1a;
            *(u64*)(gO + (rq+1) * PS + j4 + 2) = O1b;
            *(u64*)(gO + (rq+2) * PS + j4)     = O2a;
            *(u64*)(gO + (rq+2) * PS + j4 + 2) = O2b;
            *(u64*)(gO + (rq+3) * PS + j4)     = O3a;
            *(u64*)(gO + (rq+3) * PS + j4 + 2) = O3b;
        }
        __syncthreads();                                   // B
        u64 ao01 = 0, ao23 = 0;
        if (tid < 256) {
            ulonglong2 t = *(const ulonglong2*)(u + ci * PS + cj4);
            u64 aui01 = t.x, aui23 = t.y;
#pragma unroll
            for (int g = 0; g < 4; g++) {
                ADD2(aui01, aui01, *(const u64*)(pA + g * 32 * PS + ci * PS + cj4));
                ADD2(aui23, aui23, *(const u64*)(pA + g * 32 * PS + ci * PS + cj4 + 2));
                ADD2(ao01,  ao01,  *(const u64*)(pO + g * 32 * PS + ci * PS + cj4));
                ADD2(ao23,  ao23,  *(const u64*)(pO + g * 32 * PS + ci * PS + cj4 + 2));
            }
            *(u64*)(uish + ci * PS + cj4)     = aui01;
            *(u64*)(uish + ci * PS + cj4 + 2) = aui23;
        }
        __syncthreads();                                   // C
        if (tid < 256) {
            // o = ao + attn @ ui ; store
#pragma unroll
            for (int c4 = 0; c4 < 8; c4++) {
                float4 a4 = *(const float4*)(a + ci * PS + c4 * 4);
#define ASTEP(m, ac)                                                            \
                {                                                               \
                    ulonglong2 uu = *(const ulonglong2*)(uish + (c4*4 + m) * PS + cj4); \
                    u64 a2; PK2(a2, ac, ac);                                    \
                    FMA2(ao01, a2, uu.x, ao01); FMA2(ao23, a2, uu.y, ao23);     \
                }
                ASTEP(0, a4.x) ASTEP(1, a4.y) ASTEP(2, a4.z) ASTEP(3, a4.w)
#undef ASTEP
            }
            ulonglong2 ov; ov.x = ao01; ov.y = ao23;
            *(ulonglong2*)(out + ((size_t)bh * 4096 + n * 32 + ci) * 128 + sl * 32 + cj4) = ov;
        } else {
            // S += kn^T @ ui  (threads 256..511; 4 contig rows x 4 cols each)
            u64 s0a = *(const u64*)(S + (ur0 + 0) * PS + uj4);
            u64 s0b = *(const u64*)(S + (ur0 + 0) * PS + uj4 + 2);
            u64 s1a = *(const u64*)(S + (ur0 + 1) * PS + uj4);
            u64 s1b = *(const u64*)(S + (ur0 + 1) * PS + uj4 + 2);
            u64 s2a = *(const u64*)(S + (ur0 + 2) * PS + uj4);
            u64 s2b = *(const u64*)(S + (ur0 + 2) * PS + uj4 + 2);
            u64 s3a = *(const u64*)(S + (ur0 + 3) * PS + uj4);
            u64 s3b = *(const u64*)(S + (ur0 + 3) * PS + uj4 + 2);
#pragma unroll 4
            for (int c = 0; c < 32; c++) {
                float4 k4 = *(const float4*)(k + c * PW + ur0);
                ulonglong2 uu = *(const ulonglong2*)(uish + c * PS + uj4);
                u64 k0p, k1p, k2p, k3p;
                PK2(k0p, k4.x, k4.x); PK2(k1p, k4.y, k4.y);
                PK2(k2p, k4.z, k4.z); PK2(k3p, k4.w, k4.w);
                FMA2(s0a, k0p, uu.x, s0a); FMA2(s0b, k0p, uu.y, s0b);
                FMA2(s1a, k1p, uu.x, s1a); FMA2(s1b, k1p, uu.y, s1b);
                FMA2(s2a, k2p, uu.x, s2a); FMA2(s2b, k2p, uu.y, s2b);
                FMA2(s3a, k3p, uu.x, s3a); FMA2(s3b, k3p, uu.y, s3b);
            }
            *(u64*)(S + (ur0 + 0) * PS + uj4)     = s0a;
            *(u64*)(S + (ur0 + 0) * PS + uj4 + 2) = s0b;
            *(u64*)(S + (ur0 + 1) * PS + uj4)     = s1a;
            *(u64*)(S + (ur0 + 1) * PS + uj4 + 2) = s1b;
            *(u64*)(S + (ur0 + 2) * PS + uj4)     = s2a;
            *(u64*)(S + (ur0 + 2) * PS + uj4 + 2) = s2b;
            *(u64*)(S + (ur0 + 3) * PS + uj4)     = s3a;
            *(u64*)(S + (ur0 + 3) * PS + uj4 + 2) = s3b;
        }
    }
    __syncthreads();

    // final state S -> second output tensor (b,h,dk,dv)
    if (out_size >= OUT_ELEMS + S_ELEMS) {
        int ii = tid >> 3;                  // 0..63
        int jj4 = (tid & 7) << 2;
#pragma unroll
        for (int rb = 0; rb < 2; rb++) {
            int kd = ii + rb * 64;
            *(ulonglong2*)(out + OUT_ELEMS + ((size_t)bh * 128 + kd) * 128 + sl * 32 + jj4) =
                *(const ulonglong2*)(S + kd * PS + jj4);
        }
    }
}

// ---------------------------------------------------------------------------
extern "C" void kernel_launch(void* const* d_in, const int* in_sizes, int n_in,
                              void* d_out, int out_size) {
    const float* q    = (const float*)d_in[0];
    const float* k    = (const float*)d_in[1];
    const float* v    = (const float*)d_in[2];
    const float* beta = (const float*)d_in[3];
    float* out = (float*)d_out;

    const int k1_smem = (3 * 32 * PW + 4 * 1024 + 64) * 4;                       // 67,456 B
    const int k2_smem = (128 * PS + 9 * 32 * PS + 2 * BUF_FLOATS) * 4;           // 179,712 B

    cudaFuncSetAttribute(k1_kernel, cudaFuncAttributeMaxDynamicSharedMemorySize, k1_smem);
    cudaFuncSetAttribute(k2_kernel, cudaFuncAttributeMaxDynamicSharedMemorySize, k2_smem);

    k1_kernel<<<NTILES, 256, k1_smem>>>(q, k, v, beta);
    k2_kernel<<<dim3(4, 16, 2), 512, k2_smem>>>(out, out_size);
}